// round 16
// baseline (speedup 1.0000x reference)
#include <cuda_runtime.h>
#include <cuda_bf16.h>
#include <math.h>
#include <stdint.h>

#define BZ 4
#define TQ 1024
#define SK 1024
#define DM 1024
#define HH 16
#define HD 64

typedef unsigned short u16;
typedef uint32_t u32;

// ---------------------------------------------------------------------------
// Scratch (fp32)
// ---------------------------------------------------------------------------
__device__ float g_scores[(long long)BZ * HH * TQ * SK];
__device__ float g_x   [BZ * TQ * DM];
__device__ float g_x2  [BZ * TQ * DM];
__device__ float g_tv  [BZ * SK * DM];
__device__ float g_tvn [BZ * SK];

// ---------------------------------------------------------------------------
// Scratch (bf16 hi/lo split pairs)
// ---------------------------------------------------------------------------
__device__ u16 g_deh[BZ*TQ*DM],    g_del[BZ*TQ*DM];
__device__ u16 g_enh[BZ*SK*DM],    g_enl[BZ*SK*DM];
__device__ u16 g_qkvh[BZ*TQ*3*DM], g_qkvl[BZ*TQ*3*DM];
__device__ u16 g_ctxh[BZ*TQ*DM],   g_ctxl[BZ*TQ*DM];
__device__ u16 g_xh[BZ*TQ*DM],     g_xl[BZ*TQ*DM];
__device__ u16 g_q2h[BZ*TQ*DM],    g_q2l[BZ*TQ*DM];
__device__ u16 g_kv2h[BZ*SK*2*DM], g_kv2l[BZ*SK*2*DM];
__device__ u16 g_lnxh[BZ*TQ*DM],   g_lnxl[BZ*TQ*DM];
__device__ u16 g_hh[BZ*TQ*4*DM],   g_hl[BZ*TQ*4*DM];
__device__ u16 g_ph[(long long)BZ*HH*TQ*SK], g_pl[(long long)BZ*HH*TQ*SK];
// weights
__device__ u16 g_w1h[3*DM*DM],  g_w1l[3*DM*DM];
__device__ u16 g_wo1h[DM*DM],   g_wo1l[DM*DM];
__device__ u16 g_w2h[3*DM*DM],  g_w2l[3*DM*DM];
__device__ u16 g_wo2h[DM*DM],   g_wo2l[DM*DM];
__device__ u16 g_m1h[4*DM*DM],  g_m1l[4*DM*DM];
__device__ u16 g_m2h[4*DM*DM],  g_m2l[4*DM*DM];

// ---------------------------------------------------------------------------
// Streams / events
// ---------------------------------------------------------------------------
static cudaStream_t g_s1;
static cudaEvent_t  g_evRoot, g_evW1, g_evSplit, g_evSide, g_evQKV, g_evS1d;
static bool g_stream_init = []() {
    cudaStreamCreateWithFlags(&g_s1, cudaStreamNonBlocking);
    cudaEventCreateWithFlags(&g_evRoot,  cudaEventDisableTiming);
    cudaEventCreateWithFlags(&g_evW1,    cudaEventDisableTiming);
    cudaEventCreateWithFlags(&g_evSplit, cudaEventDisableTiming);
    cudaEventCreateWithFlags(&g_evSide,  cudaEventDisableTiming);
    cudaEventCreateWithFlags(&g_evQKV,   cudaEventDisableTiming);
    cudaEventCreateWithFlags(&g_evS1d,   cudaEventDisableTiming);
    return true;
}();

// ---------------------------------------------------------------------------
// Primitives
// ---------------------------------------------------------------------------
__device__ __forceinline__ u32 smem_u32(const void* p) {
    u32 a;
    asm("{ .reg .u64 t; cvta.to.shared.u64 t, %1; cvt.u32.u64 %0, t; }" : "=r"(a) : "l"(p));
    return a;
}
__device__ __forceinline__ void ldsm_x4(u32 addr, u32* r) {
    asm volatile("ldmatrix.sync.aligned.m8n8.x4.shared.b16 {%0,%1,%2,%3}, [%4];"
        : "=r"(r[0]), "=r"(r[1]), "=r"(r[2]), "=r"(r[3]) : "r"(addr));
}
__device__ __forceinline__ void ldsm_x4_t(u32 addr, u32* r) {
    asm volatile("ldmatrix.sync.aligned.m8n8.x4.trans.shared.b16 {%0,%1,%2,%3}, [%4];"
        : "=r"(r[0]), "=r"(r[1]), "=r"(r[2]), "=r"(r[3]) : "r"(addr));
}
__device__ __forceinline__ void mma_bf16(float* c, const u32* a, const u32* b) {
    asm volatile("mma.sync.aligned.m16n8k16.row.col.f32.bf16.bf16.f32 "
        "{%0,%1,%2,%3}, {%4,%5,%6,%7}, {%8,%9}, {%0,%1,%2,%3};"
        : "+f"(c[0]), "+f"(c[1]), "+f"(c[2]), "+f"(c[3])
        : "r"(a[0]), "r"(a[1]), "r"(a[2]), "r"(a[3]), "r"(b[0]), "r"(b[1]));
}
#define CP_ASYNC16(dst, src) \
    asm volatile("cp.async.cg.shared.global [%0], [%1], 16;" :: "r"(dst), "l"(src))
#define CP_COMMIT() asm volatile("cp.async.commit_group;" ::: "memory")
#define CP_WAIT(n)  asm volatile("cp.async.wait_group %0;" :: "n"(n) : "memory")

__device__ __forceinline__ void split_bf16(float f, u16& h, u16& l) {
    __nv_bfloat16 bh = __float2bfloat16(f);
    float fl = f - __bfloat162float(bh);
    h = __bfloat16_as_ushort(bh);
    l = __bfloat16_as_ushort(__float2bfloat16(fl));
}
__device__ __forceinline__ u32 packhi2(float a, float b) {
    __nv_bfloat162 t = __floats2bfloat162_rn(a, b);
    return *reinterpret_cast<u32*>(&t);
}
__device__ __forceinline__ u32 packlo2(float a, float b) {
    float la = a - __bfloat162float(__float2bfloat16(a));
    float lb = b - __bfloat162float(__float2bfloat16(b));
    return packhi2(la, lb);
}

// ---------------------------------------------------------------------------
// Elementwise split
// ---------------------------------------------------------------------------
__global__ __launch_bounds__(256)
void split_kernel(const float* __restrict__ src, u16* __restrict__ hi,
                  u16* __restrict__ lo, int n4)
{
    int i = blockIdx.x * 256 + threadIdx.x;
    if (i >= n4) return;
    float4 v = ((const float4*)src)[i];
    u16 h0,h1,h2,h3,l0,l1,l2,l3;
    split_bf16(v.x,h0,l0); split_bf16(v.y,h1,l1);
    split_bf16(v.z,h2,l2); split_bf16(v.w,h3,l3);
    ((uint2*)hi)[i] = make_uint2((u32)h0 | ((u32)h1 << 16), (u32)h2 | ((u32)h3 << 16));
    ((uint2*)lo)[i] = make_uint2((u32)l0 | ((u32)l1 << 16), (u32)l2 | ((u32)l3 << 16));
}

// ---------------------------------------------------------------------------
// Reductions
// ---------------------------------------------------------------------------
__device__ __forceinline__ float block_sum(float v, float* sh) {
#pragma unroll
    for (int o = 16; o > 0; o >>= 1) v += __shfl_xor_sync(0xffffffffu, v, o);
    if ((threadIdx.x & 31) == 0) sh[threadIdx.x >> 5] = v;
    __syncthreads();
    if (threadIdx.x < 32) {
        float w = (threadIdx.x < 8) ? sh[threadIdx.x] : 0.0f;
#pragma unroll
        for (int o = 4; o > 0; o >>= 1) w += __shfl_xor_sync(0xffffffffu, w, o);
        if (threadIdx.x == 0) sh[0] = w;
    }
    __syncthreads();
    float r = sh[0];
    __syncthreads();
    return r;
}

// ---------------------------------------------------------------------------
// LayerNorm emitting split bf16
// ---------------------------------------------------------------------------
__global__ __launch_bounds__(256)
void ln_split(const float* __restrict__ x, u16* __restrict__ yh, u16* __restrict__ yl,
              const float* __restrict__ g, const float* __restrict__ beta)
{
    __shared__ float sh[32];
    const long long row = blockIdx.x;
    const float* xr = x + row * DM;
    const int tid = threadIdx.x;
    float v[4];
    float s = 0.f, sq = 0.f;
#pragma unroll
    for (int i = 0; i < 4; i++) {
        float t = xr[tid + 256 * i];
        v[i] = t; s += t; sq += t * t;
    }
    s  = block_sum(s, sh);
    sq = block_sum(sq, sh);
    float mean = s * (1.0f / 1024.0f);
    float var  = fmaxf(sq * (1.0f / 1024.0f) - mean * mean, 0.0f);
    float inv  = rsqrtf(var + 1e-6f);
#pragma unroll
    for (int i = 0; i < 4; i++) {
        int c = tid + 256 * i;
        float y = (v[i] - mean) * inv * g[c] + beta[c];
        u16 h, l;
        split_bf16(y, h, l);
        yh[row * DM + c] = h;
        yl[row * DM + c] = l;
    }
}

// ---------------------------------------------------------------------------
// GEMM t2 (TRANSB, BN=128): 256 threads, 8 warps (2m x 4n), warp 64x32,
// S=2 double buffer, 2 CTAs/SM.
// ---------------------------------------------------------------------------
template<int ACT, bool EF32, bool ESPL>
__global__ __launch_bounds__(256, 2)
void gemm_t2(const u16* __restrict__ Ahg, const u16* __restrict__ Alg, int lda,
             long long Ab, long long Aho,
             const u16* __restrict__ Bhg, const u16* __restrict__ Blg, int ldb,
             long long Bb, long long Bho,
             float* __restrict__ Cf, u16* __restrict__ Chg, u16* __restrict__ Clg,
             int ldc, long long Cb, long long Cho,
             const float* __restrict__ bias,
             const float* __restrict__ res, int ldr,
             int K, float alpha, int nh)
{
    constexpr int PA = 40;
    constexpr int ASZ = 128 * PA;
    constexpr int BSZ = 128 * PA;
    constexpr int STAGE = 2 * ASZ + 2 * BSZ;

    extern __shared__ __align__(128) u16 sm[];

    const int tid = threadIdx.x;
    const int lane = tid & 31;
    const int wid = tid >> 5;
    const int wm = (wid & 1) * 64;
    const int wn = (wid >> 1) * 32;

    const int bz = blockIdx.z;
    const int bb = bz / nh;
    const int hh = bz - bb * nh;
    const int m0 = blockIdx.y * 128;
    const int n0 = blockIdx.x * 128;

    const u16* Ah = Ahg + bb * Ab + hh * Aho + (long long)m0 * lda;
    const u16* Al = Alg + bb * Ab + hh * Aho + (long long)m0 * lda;
    const u16* Bh = Bhg + bb * Bb + hh * Bho + (long long)n0 * ldb;
    const u16* Bl = Blg + bb * Bb + hh * Bho + (long long)n0 * ldb;

    float acc[4][4][4];
#pragma unroll
    for (int mi = 0; mi < 4; mi++)
#pragma unroll
        for (int ni = 0; ni < 4; ni++)
#pragma unroll
            for (int j = 0; j < 4; j++) acc[mi][ni][j] = 0.0f;

    const u32 sb0 = smem_u32(sm);
    const int nk = K >> 5;

    auto issue = [&](int k) {
        const int slot = k & 1;
        const int k0 = k << 5;
        const u32 st = sb0 + (u32)(slot * STAGE) * 2;
#pragma unroll
        for (int u = 0; u < 2; u++) {
            const int idx = tid + u * 256;
            const int row = idx >> 2, c = idx & 3;
            const long long oa = (long long)row * lda + k0 + c * 8;
            const long long ob = (long long)row * ldb + k0 + c * 8;
            const u32 da = st + (u32)(row * PA + c * 8) * 2;
            CP_ASYNC16(da, (const void*)(Ah + oa));
            CP_ASYNC16(da + (u32)ASZ * 2, (const void*)(Al + oa));
            CP_ASYNC16(da + (u32)ASZ * 4, (const void*)(Bh + ob));
            CP_ASYNC16(da + (u32)ASZ * 4 + (u32)BSZ * 2, (const void*)(Bl + ob));
        }
    };

    issue(0);
    CP_COMMIT();

    for (int k = 0; k < nk; k++) {
        CP_WAIT(0);
        __syncthreads();
        if (k + 1 < nk) issue(k + 1);
        CP_COMMIT();

        const u32 base = sb0 + (u32)((k & 1) * STAGE) * 2;
#pragma unroll
        for (int kk = 0; kk < 32; kk += 16) {
            u32 bh_[4][2], bl_[4][2];
            {
                const int brow = wn + (lane & 7) + ((lane & 16) >> 1);
                const int bcol = kk + (((lane >> 3) & 1) << 3);
#pragma unroll
                for (int nj = 0; nj < 2; nj++) {
                    u32 bd = base + (u32)(2 * ASZ + (brow + nj * 16) * PA + bcol) * 2;
                    u32 r[4];
                    ldsm_x4(bd, r);
                    bh_[2*nj][0]=r[0]; bh_[2*nj][1]=r[1];
                    bh_[2*nj+1][0]=r[2]; bh_[2*nj+1][1]=r[3];
                    ldsm_x4(bd + (u32)BSZ * 2, r);
                    bl_[2*nj][0]=r[0]; bl_[2*nj][1]=r[1];
                    bl_[2*nj+1][0]=r[2]; bl_[2*nj+1][1]=r[3];
                }
            }
            const int arow = wm + (lane & 15);
            const int acol = kk + ((lane >> 4) << 3);
#pragma unroll
            for (int mi = 0; mi < 4; mi++) {
                u32 ah[4], al_[4];
                u32 ad = base + (u32)(((arow + mi * 16) * PA) + acol) * 2;
                ldsm_x4(ad, ah);
                ldsm_x4(ad + (u32)ASZ * 2, al_);
#pragma unroll
                for (int ni = 0; ni < 4; ni++) {
                    mma_bf16(acc[mi][ni], ah, bh_[ni]);
                    mma_bf16(acc[mi][ni], ah, bl_[ni]);
                    mma_bf16(acc[mi][ni], al_, bh_[ni]);
                }
            }
        }
    }

    float* Cfg = EF32 ? (Cf + bb * Cb + hh * Cho) : nullptr;
    u16* Chh = ESPL ? (Chg + bb * Cb + hh * Cho) : nullptr;
    u16* Cll = ESPL ? (Clg + bb * Cb + hh * Cho) : nullptr;
#pragma unroll
    for (int mi = 0; mi < 4; mi++) {
#pragma unroll
        for (int ni = 0; ni < 4; ni++) {
            int m = m0 + wm + mi * 16 + (lane >> 2);
            int n = n0 + wn + ni * 8 + (lane & 3) * 2;
#pragma unroll
            for (int rr = 0; rr < 2; rr++) {
                int mm = m + rr * 8;
                float v0 = acc[mi][ni][rr * 2 + 0] * alpha;
                float v1 = acc[mi][ni][rr * 2 + 1] * alpha;
                if (bias) { v0 += bias[n]; v1 += bias[n + 1]; }
                if (ACT == 1) {
                    v0 = 0.5f * v0 * (1.0f + erff(v0 * 0.70710678118654752f));
                    v1 = 0.5f * v1 * (1.0f + erff(v1 * 0.70710678118654752f));
                }
                if (res) {
                    v0 += res[(long long)mm * ldr + n];
                    v1 += res[(long long)mm * ldr + n + 1];
                }
                long long co = (long long)mm * ldc + n;
                if (EF32) *(float2*)(Cfg + co) = make_float2(v0, v1);
                if (ESPL) {
                    *(u32*)(Chh + co) = packhi2(v0, v1);
                    *(u32*)(Cll + co) = packlo2(v0, v1);
                }
            }
        }
    }
}

// ---------------------------------------------------------------------------
// GEMM t2n (non-TRANSB): B[K,N] staged [32][BN+8] + ldsm.trans. S=2.
// ---------------------------------------------------------------------------
template<int BN, bool EF32, bool ESPL>
__global__ __launch_bounds__(256, 2)
void gemm_t2n(const u16* __restrict__ Ahg, const u16* __restrict__ Alg, int lda,
              long long Ab, long long Aho,
              const u16* __restrict__ Bhg, const u16* __restrict__ Blg, int ldb,
              long long Bb, long long Bho,
              float* __restrict__ Cf, u16* __restrict__ Chg, u16* __restrict__ Clg,
              int ldc, long long Cb, long long Cho,
              const float* __restrict__ bias,
              const float* __restrict__ res, int ldr,
              int K, float alpha, int nh)
{
    constexpr int PA = 40;
    constexpr int ASZ = 128 * PA;
    constexpr int PB = BN + 8;
    constexpr int BSZ = 32 * PB;
    constexpr int STAGE = 2 * ASZ + 2 * BSZ;
    constexpr int WN = BN / 4;
    constexpr int NT = WN / 8;

    extern __shared__ __align__(128) u16 sm[];

    const int tid = threadIdx.x;
    const int lane = tid & 31;
    const int wid = tid >> 5;
    const int wm = (wid & 1) * 64;
    const int wn = (wid >> 1) * WN;

    const int bz = blockIdx.z;
    const int bb = bz / nh;
    const int hh = bz - bb * nh;
    const int m0 = blockIdx.y * 128;
    const int n0 = blockIdx.x * BN;

    const u16* Ah = Ahg + bb * Ab + hh * Aho + (long long)m0 * lda;
    const u16* Al = Alg + bb * Ab + hh * Aho + (long long)m0 * lda;
    const u16* Bh = Bhg + bb * Bb + hh * Bho + (long long)n0;
    const u16* Bl = Blg + bb * Bb + hh * Bho + (long long)n0;

    float acc[4][NT][4];
#pragma unroll
    for (int mi = 0; mi < 4; mi++)
#pragma unroll
        for (int ni = 0; ni < NT; ni++)
#pragma unroll
            for (int j = 0; j < 4; j++) acc[mi][ni][j] = 0.0f;

    const u32 sb0 = smem_u32(sm);
    const int nk = K >> 5;

    auto issue = [&](int k) {
        const int slot = k & 1;
        const int k0 = k << 5;
        const u32 st = sb0 + (u32)(slot * STAGE) * 2;
#pragma unroll
        for (int u = 0; u < 2; u++) {
            const int idx = tid + u * 256;
            const int row = idx >> 2, c = idx & 3;
            const long long oa = (long long)row * lda + k0 + c * 8;
            const u32 da = st + (u32)(row * PA + c * 8) * 2;
            CP_ASYNC16(da, (const void*)(Ah + oa));
            CP_ASYNC16(da + (u32)ASZ * 2, (const void*)(Al + oa));
        }
#pragma unroll
        for (int u = 0; u < BN / 64; u++) {
            const int idx = tid + u * 256;
            const int row = (BN == 128) ? (idx >> 4) : (idx >> 3);
            const int c   = (BN == 128) ? (idx & 15) : (idx & 7);
            const long long o = (long long)(k0 + row) * ldb + c * 8;
            const u32 d = st + (u32)(2 * ASZ + row * PB + c * 8) * 2;
            CP_ASYNC16(d, (const void*)(Bh + o));
            CP_ASYNC16(d + (u32)BSZ * 2, (const void*)(Bl + o));
        }
    };

    issue(0);
    CP_COMMIT();

    for (int k = 0; k < nk; k++) {
        CP_WAIT(0);
        __syncthreads();
        if (k + 1 < nk) issue(k + 1);
        CP_COMMIT();

        const u32 base = sb0 + (u32)((k & 1) * STAGE) * 2;
#pragma unroll
        for (int kk = 0; kk < 32; kk += 16) {
            u32 bh_[NT][2], bl_[NT][2];
            {
                const int brow = kk + (lane & 15);
#pragma unroll
                for (int nj = 0; nj < NT / 2; nj++) {
                    const int bcol = wn + nj * 16 + ((lane >> 4) << 3);
                    u32 bd = base + (u32)(2 * ASZ + brow * PB + bcol) * 2;
                    u32 r[4];
                    ldsm_x4_t(bd, r);
                    bh_[2*nj][0]=r[0]; bh_[2*nj][1]=r[1];
                    bh_[2*nj+1][0]=r[2]; bh_[2*nj+1][1]=r[3];
                    ldsm_x4_t(bd + (u32)BSZ * 2, r);
                    bl_[2*nj][0]=r[0]; bl_[2*nj][1]=r[1];
                    bl_[2*nj+1][0]=r[2]; bl_[2*nj+1][1]=r[3];
                }
            }
            const int arow = wm + (lane & 15);
            const int acol = kk + ((lane >> 4) << 3);
#pragma unroll
            for (int mi = 0; mi < 4; mi++) {
                u32 ah[4], al_[4];
                u32 ad = base + (u32)(((arow + mi * 16) * PA) + acol) * 2;
                ldsm_x4(ad, ah);
                ldsm_x4(ad + (u32)ASZ * 2, al_);
#pragma unroll
                for (int ni = 0; ni < NT; ni++) {
                    mma_bf16(acc[mi][ni], ah, bh_[ni]);
                    mma_bf16(acc[mi][ni], ah, bl_[ni]);
                    mma_bf16(acc[mi][ni], al_, bh_[ni]);
                }
            }
        }
    }

    float* Cfg = EF32 ? (Cf + bb * Cb + hh * Cho) : nullptr;
    u16* Chh = ESPL ? (Chg + bb * Cb + hh * Cho) : nullptr;
    u16* Cll = ESPL ? (Clg + bb * Cb + hh * Cho) : nullptr;
#pragma unroll
    for (int mi = 0; mi < 4; mi++) {
#pragma unroll
        for (int ni = 0; ni < NT; ni++) {
            int m = m0 + wm + mi * 16 + (lane >> 2);
            int n = n0 + wn + ni * 8 + (lane & 3) * 2;
#pragma unroll
            for (int rr = 0; rr < 2; rr++) {
                int mm = m + rr * 8;
                float v0 = acc[mi][ni][rr * 2 + 0] * alpha;
                float v1 = acc[mi][ni][rr * 2 + 1] * alpha;
                if (bias) { v0 += bias[n]; v1 += bias[n + 1]; }
                if (res) {
                    v0 += res[(long long)mm * ldr + n];
                    v1 += res[(long long)mm * ldr + n + 1];
                }
                long long co = (long long)mm * ldc + n;
                if (EF32) *(float2*)(Cfg + co) = make_float2(v0, v1);
                if (ESPL) {
                    *(u32*)(Chh + co) = packhi2(v0, v1);
                    *(u32*)(Cll + co) = packlo2(v0, v1);
                }
            }
        }
    }
}

// ---------------------------------------------------------------------------
// Flash self-attention v2
// ---------------------------------------------------------------------------
__global__ __launch_bounds__(256)
void flash_self(const u16* __restrict__ qh, const u16* __restrict__ ql,
                const unsigned char* __restrict__ kpm,
                u16* __restrict__ ch, u16* __restrict__ cl)
{
    constexpr int P = 72;
    constexpr int TSZ = 64 * P;
    constexpr int QTSZ = 128 * P;
    extern __shared__ __align__(128) u16 fs[];
    unsigned char* smask = (unsigned char*)(fs + 2 * QTSZ + 8 * TSZ);

    const int tid = threadIdx.x, lane = tid & 31, wid = tid >> 5;
    const int bx = blockIdx.x;
    const int bh = blockIdx.y;
    const int b = bh >> 4, h = bh & 15;
    const int t0 = bx * 128;

    const long long qoff = ((long long)b * TQ + t0) * 3 * DM + h * HD;
    const long long koff = ((long long)b * TQ) * 3 * DM + DM + h * HD;
    const long long voff = ((long long)b * TQ) * 3 * DM + 2 * DM + h * HD;
    const unsigned char* kp = kpm + (long long)b * SK;

    const u32 fsb = smem_u32(fs);
    const u32 kvb0 = fsb + (u32)(2 * QTSZ) * 2;

    auto issueKV = [&](int ch_i, int bufi) {
        const int s0 = ch_i * 64;
        const u32 kvb = kvb0 + (u32)(bufi * 4 * TSZ) * 2;
#pragma unroll
        for (int u = 0; u < 2; u++) {
            int idx = tid + u * 256;
            int r = idx >> 3, c8 = idx & 7;
            long long ko = koff + (long long)(s0 + r) * 3 * DM + c8 * 8;
            long long vo = voff + (long long)(s0 + r) * 3 * DM + c8 * 8;
            u32 d = kvb + (u32)(r * P + c8 * 8) * 2;
            CP_ASYNC16(d,                (const void*)(qh + ko));
            CP_ASYNC16(d + (u32)TSZ * 2, (const void*)(ql + ko));
            CP_ASYNC16(d + (u32)TSZ * 4, (const void*)(qh + vo));
            CP_ASYNC16(d + (u32)TSZ * 6, (const void*)(ql + vo));
        }
    };

    issueKV(0, 0);
    CP_COMMIT();
#pragma unroll
    for (int u = 0; u < 4; u++) {
        int idx = tid + u * 256;
        int r = idx >> 3, c8 = idx & 7;
        long long o = qoff + (long long)r * 3 * DM + c8 * 8;
        int off = r * P + c8 * 8;
        *(uint4*)(fs + off)        = *(const uint4*)(qh + o);
        *(uint4*)(fs + QTSZ + off) = *(const uint4*)(ql + o);
    }
    if (tid < 64) smask[tid] = kp[tid];

    float o_[8][4];
#pragma unroll
    for (int i = 0; i < 8; i++)
#pragma unroll
        for (int j = 0; j < 4; j++) o_[i][j] = 0.0f;
    float mrow0 = -1e30f, mrow1 = -1e30f, lrow0 = 0.0f, lrow1 = 0.0f;

    const int warp_last_row = t0 + wid * 16 + 15;
    const int nch = 2 * (bx + 1);
    int buf = 0;
    for (int ch_i = 0; ch_i < nch; ch_i++) {
        const int s0 = ch_i * 64;
        CP_WAIT(0);
        __syncthreads();
        if (ch_i + 1 < nch) {
            issueKV(ch_i + 1, buf ^ 1);
            if (tid < 64) smask[(buf ^ 1) * 64 + tid] = kp[s0 + 64 + tid];
        }
        CP_COMMIT();

        if (s0 <= warp_last_row) {
            const u32 kb = kvb0 + (u32)(buf * 4 * TSZ) * 2;
            const u32 vb = kb + (u32)TSZ * 4;
            const unsigned char* mk = smask + buf * 64;

            float sc[8][4];
#pragma unroll
            for (int i = 0; i < 8; i++)
#pragma unroll
                for (int j = 0; j < 4; j++) sc[i][j] = 0.0f;

#pragma unroll
            for (int kt = 0; kt < 4; kt++) {
                u32 aq[4], al_[4];
                u32 ad = fsb + (u32)(((wid * 16 + (lane & 15)) * P + kt * 16 + ((lane >> 4) << 3))) * 2;
                ldsm_x4(ad, aq);
                ldsm_x4(ad + (u32)QTSZ * 2, al_);
                u32 bh_[8][2], bl_[8][2];
#pragma unroll
                for (int nj = 0; nj < 4; nj++) {
                    u32 bd = kb + (u32)(((nj * 16 + (lane & 7) + ((lane & 16) >> 1)) * P
                                        + kt * 16 + (((lane >> 3) & 1) << 3))) * 2;
                    u32 r[4];
                    ldsm_x4(bd, r);
                    bh_[2*nj][0]=r[0]; bh_[2*nj][1]=r[1]; bh_[2*nj+1][0]=r[2]; bh_[2*nj+1][1]=r[3];
                    ldsm_x4(bd + (u32)TSZ * 2, r);
                    bl_[2*nj][0]=r[0]; bl_[2*nj][1]=r[1]; bl_[2*nj+1][0]=r[2]; bl_[2*nj+1][1]=r[3];
                }
#pragma unroll
                for (int ni = 0; ni < 8; ni++) {
                    mma_bf16(sc[ni], aq, bh_[ni]);
                    mma_bf16(sc[ni], aq, bl_[ni]);
                    mma_bf16(sc[ni], al_, bh_[ni]);
                }
            }

            const int gr0 = t0 + wid * 16 + (lane >> 2);
#pragma unroll
            for (int ni = 0; ni < 8; ni++) {
#pragma unroll
                for (int j = 0; j < 4; j++) {
                    int rr = gr0 + ((j >> 1) << 3);
                    int cl_ = ni * 8 + (lane & 3) * 2 + (j & 1);
                    float xv = sc[ni][j] * 0.125f;
                    if (s0 + cl_ > rr) xv -= 1e9f;
                    if (mk[cl_]) xv = -1e9f;
                    sc[ni][j] = xv;
                }
            }

            float mc0 = -1e30f, mc1 = -1e30f;
#pragma unroll
            for (int ni = 0; ni < 8; ni++) {
                mc0 = fmaxf(mc0, fmaxf(sc[ni][0], sc[ni][1]));
                mc1 = fmaxf(mc1, fmaxf(sc[ni][2], sc[ni][3]));
            }
#pragma unroll
            for (int off = 1; off <= 2; off <<= 1) {
                mc0 = fmaxf(mc0, __shfl_xor_sync(0xffffffffu, mc0, off));
                mc1 = fmaxf(mc1, __shfl_xor_sync(0xffffffffu, mc1, off));
            }
            float mn0 = fmaxf(mrow0, mc0), mn1 = fmaxf(mrow1, mc1);
            float scale0 = __expf(mrow0 - mn0), scale1 = __expf(mrow1 - mn1);
            float ls0 = 0.0f, ls1 = 0.0f;
#pragma unroll
            for (int ni = 0; ni < 8; ni++) {
                sc[ni][0] = __expf(sc[ni][0] - mn0);
                sc[ni][1] = __expf(sc[ni][1] - mn0);
                sc[ni][2] = __expf(sc[ni][2] - mn1);
                sc[ni][3] = __expf(sc[ni][3] - mn1);
                ls0 += sc[ni][0] + sc[ni][1];
                ls1 += sc[ni][2] + sc[ni][3];
            }
#pragma unroll
            for (int off = 1; off <= 2; off <<= 1) {
                ls0 += __shfl_xor_sync(0xffffffffu, ls0, off);
                ls1 += __shfl_xor_sync(0xffffffffu, ls1, off);
            }
            lrow0 = lrow0 * scale0 + ls0;
            lrow1 = lrow1 * scale1 + ls1;
            mrow0 = mn0; mrow1 = mn1;
#pragma unroll
            for (int ni = 0; ni < 8; ni++) {
                o_[ni][0] *= scale0; o_[ni][1] *= scale0;
                o_[ni][2] *= scale1; o_[ni][3] *= scale1;
            }

#pragma unroll
            for (int kt = 0; kt < 4; kt++) {
                u32 ph[4], pl[4];
                ph[0] = packhi2(sc[2*kt][0],   sc[2*kt][1]);
                ph[1] = packhi2(sc[2*kt][2],   sc[2*kt][3]);
                ph[2] = packhi2(sc[2*kt+1][0], sc[2*kt+1][1]);
                ph[3] = packhi2(sc[2*kt+1][2], sc[2*kt+1][3]);
                pl[0] = packlo2(sc[2*kt][0],   sc[2*kt][1]);
                pl[1] = packlo2(sc[2*kt][2],   sc[2*kt][3]);
                pl[2] = packlo2(sc[2*kt+1][0], sc[2*kt+1][1]);
                pl[3] = packlo2(sc[2*kt+1][2], sc[2*kt+1][3]);

                u32 vh_[8][2], vl_[8][2];
#pragma unroll
                for (int nj = 0; nj < 4; nj++) {
                    u32 bd = vb + (u32)(((kt * 16 + (lane & 15)) * P
                                        + nj * 16 + ((lane >> 4) << 3))) * 2;
                    u32 r[4];
                    ldsm_x4_t(bd, r);
                    vh_[2*nj][0]=r[0]; vh_[2*nj][1]=r[1]; vh_[2*nj+1][0]=r[2]; vh_[2*nj+1][1]=r[3];
                    ldsm_x4_t(bd + (u32)TSZ * 2, r);
                    vl_[2*nj][0]=r[0]; vl_[2*nj][1]=r[1]; vl_[2*nj+1][0]=r[2]; vl_[2*nj+1][1]=r[3];
                }
#pragma unroll
                for (int ni = 0; ni < 8; ni++) {
                    mma_bf16(o_[ni], ph, vh_[ni]);
                    mma_bf16(o_[ni], ph, vl_[ni]);
                    mma_bf16(o_[ni], pl, vh_[ni]);
                }
            }
        }
        buf ^= 1;
    }

    float inv0 = 1.0f / fmaxf(lrow0, 1e-30f);
    float inv1 = 1.0f / fmaxf(lrow1, 1e-30f);
    const long long cbase = ((long long)b * TQ) * DM + h * HD;
    const int r0 = t0 + wid * 16 + (lane >> 2);
#pragma unroll
    for (int ni = 0; ni < 8; ni++) {
        int c = ni * 8 + (lane & 3) * 2;
        long long o0 = cbase + (long long)r0 * DM + c;
        long long o1 = cbase + (long long)(r0 + 8) * DM + c;
        *(u32*)(ch + o0) = packhi2(o_[ni][0] * inv0, o_[ni][1] * inv0);
        *(u32*)(cl + o0) = packlo2(o_[ni][0] * inv0, o_[ni][1] * inv0);
        *(u32*)(ch + o1) = packhi2(o_[ni][2] * inv1, o_[ni][3] * inv1);
        *(u32*)(cl + o1) = packlo2(o_[ni][2] * inv1, o_[ni][3] * inv1);
    }
}

// ---------------------------------------------------------------------------
// Fused cross softmax v2 (warp-per-row)
// ---------------------------------------------------------------------------
__global__ __launch_bounds__(256)
void softmax_fused(const float* __restrict__ sc, const unsigned char* __restrict__ kpm,
                   const float* __restrict__ tvn,
                   u16* __restrict__ ph, u16* __restrict__ pl, float* __restrict__ out2)
{
    __shared__ unsigned char km[SK];
    const int lane = threadIdx.x & 31, warp = threadIdx.x >> 5;
    const int t = blockIdx.x * 8 + warp;
    const int b = blockIdx.y;
    for (int i = threadIdx.x; i < SK; i += 256) km[i] = kpm[(long long)b * SK + i];
    __syncthreads();

    float psum[32];
#pragma unroll
    for (int i = 0; i < 32; i++) psum[i] = 0.0f;

    unsigned char mk[32];
#pragma unroll
    for (int j = 0; j < 8; j++) {
        int s0 = (lane + 32 * j) * 4;
#pragma unroll
        for (int c = 0; c < 4; c++) mk[4 * j + c] = km[s0 + c];
    }

    for (int h = 0; h < HH; h++) {
        const long long roff = (((long long)(b * HH + h)) * TQ + t) * SK;
        float v[32];
        float mx = -3.4e38f;
#pragma unroll
        for (int j = 0; j < 8; j++) {
            float4 v4 = *(const float4*)(sc + roff + (lane + 32 * j) * 4);
            v[4*j+0] = mk[4*j+0] ? -1e9f : v4.x;
            v[4*j+1] = mk[4*j+1] ? -1e9f : v4.y;
            v[4*j+2] = mk[4*j+2] ? -1e9f : v4.z;
            v[4*j+3] = mk[4*j+3] ? -1e9f : v4.w;
#pragma unroll
            for (int c = 0; c < 4; c++) mx = fmaxf(mx, v[4*j+c]);
        }
#pragma unroll
        for (int o = 16; o > 0; o >>= 1) mx = fmaxf(mx, __shfl_xor_sync(0xffffffffu, mx, o));
        float sum = 0.0f;
#pragma unroll
        for (int i = 0; i < 32; i++) {
            v[i] = __expf(v[i] - mx);
            sum += v[i];
        }
#pragma unroll
        for (int o = 16; o > 0; o >>= 1) sum += __shfl_xor_sync(0xffffffffu, sum, o);
        float inv = 1.0f / sum;
#pragma unroll
        for (int j = 0; j < 8; j++) {
            float p0 = v[4*j+0] * inv, p1 = v[4*j+1] * inv;
            float p2 = v[4*j+2] * inv, p3 = v[4*j+3] * inv;
            psum[4*j+0] += p0; psum[4*j+1] += p1;
            psum[4*j+2] += p2; psum[4*j+3] += p3;
            long long so = roff + (lane + 32 * j) * 4;
            *(uint2*)(ph + so) = make_uint2(packhi2(p0, p1), packhi2(p2, p3));
            *(uint2*)(pl + so) = make_uint2(packlo2(p0, p1), packlo2(p2, p3));
        }
    }

    const long long obase = ((long long)b * TQ + t) * SK;
    const float* tvb = tvn + b * SK;
#pragma unroll
    for (int j = 0; j < 8; j++) {
        int s0 = (lane + 32 * j) * 4;
        float4 tv4 = *(const float4*)(tvb + s0);
        float4 o4 = make_float4(psum[4*j+0] * (1.0f/16.0f) * tv4.x,
                                psum[4*j+1] * (1.0f/16.0f) * tv4.y,
                                psum[4*j+2] * (1.0f/16.0f) * tv4.z,
                                psum[4*j+3] * (1.0f/16.0f) * tv4.w);
        *(float4*)(out2 + obase + s0) = o4;
    }
}

// ---------------------------------------------------------------------------
// Row L2 norm
// ---------------------------------------------------------------------------
__global__ __launch_bounds__(256)
void rownorm_kernel(const float* __restrict__ x, float* __restrict__ out)
{
    __shared__ float sh[32];
    const long long row = blockIdx.x;
    const float* xr = x + row * DM;
    float sq = 0.f;
#pragma unroll
    for (int i = 0; i < 4; i++) {
        float t = xr[threadIdx.x + 256 * i];
        sq += t * t;
    }
    sq = block_sum(sq, sh);
    if (threadIdx.x == 0) out[row] = sqrtf(sq);
}

// ---------------------------------------------------------------------------
// Host launcher — dual-stream, batch-halved from flash onward
// ---------------------------------------------------------------------------
extern "C" void kernel_launch(void* const* d_in, const int* in_sizes, int n_in,
                              void* d_out, int out_size)
{
    const float* dec_in  = (const float*)d_in[0];
    const float* enc_out = (const float*)d_in[1];
    const unsigned char* en_mask = (const unsigned char*)d_in[2];
    const unsigned char* de_mask = (const unsigned char*)d_in[3];
    const float* ln_g   = (const float*)d_in[4];
    const float* ln_b   = (const float*)d_in[5];
    const float* w_in1  = (const float*)d_in[6];
    const float* b_in1  = (const float*)d_in[7];
    const float* w_out1 = (const float*)d_in[8];
    const float* b_out1 = (const float*)d_in[9];
    const float* w_in2  = (const float*)d_in[10];
    const float* b_in2  = (const float*)d_in[11];
    const float* w_out2 = (const float*)d_in[12];
    const float* b_out2 = (const float*)d_in[13];
    const float* mlp_w1 = (const float*)d_in[14];
    const float* mlp_b1 = (const float*)d_in[15];
    const float* mlp_w2 = (const float*)d_in[16];
    const float* mlp_b2 = (const float*)d_in[17];

    float *scores, *x, *x2, *tv, *tvn;
    cudaGetSymbolAddress((void**)&scores, g_scores);
    cudaGetSymbolAddress((void**)&x,  g_x);
    cudaGetSymbolAddress((void**)&x2, g_x2);
    cudaGetSymbolAddress((void**)&tv, g_tv);
    cudaGetSymbolAddress((void**)&tvn, g_tvn);

    u16 *deh,*del,*enh,*enl,*qkvh,*qkvl,*ctxh,*ctxl,*xh,*xl,*q2h,*q2l,*kv2h,*kv2l;
    u16 *lnxh,*lnxl,*hhp,*hlp,*ph,*pl;
    u16 *w1h,*w1l,*wo1h,*wo1l,*w2h,*w2l,*wo2h,*wo2l,*m1h,*m1l,*m2h,*m2l;
    cudaGetSymbolAddress((void**)&deh, g_deh);   cudaGetSymbolAddress((void**)&del, g_del);
    cudaGetSymbolAddress((void**)&enh, g_enh);   cudaGetSymbolAddress((void**)&enl, g_enl);
    cudaGetSymbolAddress((void**)&qkvh, g_qkvh); cudaGetSymbolAddress((void**)&qkvl, g_qkvl);
    cudaGetSymbolAddress((void**)&ctxh, g_ctxh); cudaGetSymbolAddress((void**)&ctxl, g_ctxl);
    cudaGetSymbolAddress((void**)&xh, g_xh);     cudaGetSymbolAddress((void**)&xl, g_xl);
    cudaGetSymbolAddress((void**)&q2h, g_q2h);   cudaGetSymbolAddress((void**)&q2l, g_q2l);
    cudaGetSymbolAddress((void**)&kv2h, g_kv2h); cudaGetSymbolAddress((void**)&kv2l, g_kv2l);
    cudaGetSymbolAddress((void**)&lnxh, g_lnxh); cudaGetSymbolAddress((void**)&lnxl, g_lnxl);
    cudaGetSymbolAddress((void**)&hhp, g_hh);    cudaGetSymbolAddress((void**)&hlp, g_hl);
    cudaGetSymbolAddress((void**)&ph, g_ph);     cudaGetSymbolAddress((void**)&pl, g_pl);
    cudaGetSymbolAddress((void**)&w1h, g_w1h);   cudaGetSymbolAddress((void**)&w1l, g_w1l);
    cudaGetSymbolAddress((void**)&wo1h, g_wo1h); cudaGetSymbolAddress((void**)&wo1l, g_wo1l);
    cudaGetSymbolAddress((void**)&w2h, g_w2h);   cudaGetSymbolAddress((void**)&w2l, g_w2l);
    cudaGetSymbolAddress((void**)&wo2h, g_wo2h); cudaGetSymbolAddress((void**)&wo2l, g_wo2l);
    cudaGetSymbolAddress((void**)&m1h, g_m1h);   cudaGetSymbolAddress((void**)&m1l, g_m1l);
    cudaGetSymbolAddress((void**)&m2h, g_m2h);   cudaGetSymbolAddress((void**)&m2l, g_m2l);

    float* out1 = (float*)d_out;
    float* out2 = (float*)d_out + (long long)BZ * TQ * DM;

    const int BT = BZ * TQ;
    const long long TSh = (long long)TQ * SK;
    const long long TSb = (long long)HH * TQ * SK;

    const int SM_T2   = 2 * (4 * 128 * 40) * 2;                    //  81920
    const int SM_T2N128 = 2 * (2 * 128 * 40 + 2 * 32 * 136) * 2;   //  75776
    const int SM_T2N64  = 2 * (2 * 128 * 40 + 2 * 32 * 72)  * 2;   //  59392
    const int SMFL    = (2 * 128 * 72 + 8 * 64 * 72) * 2 + 128;    // 110720
    cudaFuncSetAttribute(gemm_t2<0,false,true >, cudaFuncAttributeMaxDynamicSharedMemorySize, SM_T2);
    cudaFuncSetAttribute(gemm_t2<0,true ,true >, cudaFuncAttributeMaxDynamicSharedMemorySize, SM_T2);
    cudaFuncSetAttribute(gemm_t2<0,true ,false>, cudaFuncAttributeMaxDynamicSharedMemorySize, SM_T2);
    cudaFuncSetAttribute(gemm_t2<1,false,true >, cudaFuncAttributeMaxDynamicSharedMemorySize, SM_T2);
    cudaFuncSetAttribute(gemm_t2n<128,true ,false>, cudaFuncAttributeMaxDynamicSharedMemorySize, SM_T2N128);
    cudaFuncSetAttribute(gemm_t2n<64 ,false,true >, cudaFuncAttributeMaxDynamicSharedMemorySize, SM_T2N64);
    cudaFuncSetAttribute(flash_self, cudaFuncAttributeMaxDynamicSharedMemorySize, SMFL);

    cudaStream_t s0 = 0;
    cudaStream_t s1 = g_s1;

    cudaEventRecord(g_evRoot, s0);
    cudaStreamWaitEvent(s1, g_evRoot, 0);

    // ---- side stream: w1 split first (feeds s0 QKV), then the rest ----
    split_kernel<<<(3*DM*DM/4 + 255)/256, 256, 0, s1>>>(w_in1, w1h, w1l, 3*DM*DM/4);
    cudaEventRecord(g_evW1, s1);
    split_kernel<<<(DM*DM/4   + 255)/256, 256, 0, s1>>>(w_out1, wo1h, wo1l, DM*DM/4);
    split_kernel<<<(3*DM*DM/4 + 255)/256, 256, 0, s1>>>(w_in2,  w2h,  w2l,  3*DM*DM/4);
    split_kernel<<<(DM*DM/4   + 255)/256, 256, 0, s1>>>(w_out2, wo2h, wo2l, DM*DM/4);
    split_kernel<<<(4*DM*DM/4 + 255)/256, 256, 0, s1>>>(mlp_w1, m1h,  m1l,  4*DM*DM/4);
    split_kernel<<<(4*DM*DM/4 + 255)/256, 256, 0, s1>>>(mlp_w2, m2h,  m2l,  4*DM*DM/4);
    cudaEventRecord(g_evSplit, s1);

    ln_split<<<BT, 256, 0, s1>>>(enc_out, enh, enl, ln_g, ln_b);
    gemm_t2<0,false,true><<<dim3(2*DM/128, BT/128, 1), 256, SM_T2, s1>>>(
        enh, enl, DM, 0, 0,  w2h + (long long)DM*DM, w2l + (long long)DM*DM, DM, 0, 0,
        nullptr, kv2h, kv2l, 2*DM, 0, 0,
        b_in2 + DM, nullptr, 0, DM, 1.0f, 1);
    gemm_t2n<128,true,false><<<dim3(DM/128, BT/128, 1), 256, SM_T2N128, s1>>>(
        enh, enl, DM, 0, 0,  wo2h, wo2l, DM, 0, 0,
        tv, nullptr, nullptr, DM, 0, 0,
        nullptr, nullptr, 0, DM, 1.0f, 1);
    rownorm_kernel<<<BT, 256, 0, s1>>>(tv, tvn);
    cudaEventRecord(g_evSide, s1);

    // ---- main stream: shared decoder head (full batch) ----
    ln_split<<<BT, 256, 0, s0>>>(dec_in, deh, del, ln_g, ln_b);
    cudaStreamWaitEvent(s0, g_evW1, 0);

    gemm_t2<0,false,true><<<dim3(3*DM/128, BT/128, 1), 256, SM_T2, s0>>>(
        deh, del, DM, 0, 0,  w1h, w1l, DM, 0, 0,
        nullptr, qkvh, qkvl, 3*DM, 0, 0,
        b_in1, nullptr, 0, DM, 1.0f, 1);
    cudaEventRecord(g_evQKV, s0);

    // s0 half0 needs weight splits + kv2/tvn at the right points:
    cudaStreamWaitEvent(s0, g_evSplit, 0);  // before proj1 h0 (flash h0 first anyway)
    // s1 half1 needs QKV:
    cudaStreamWaitEvent(s1, g_evQKV, 0);

    // ---- per-half chains: flash -> proj1 -> q2 -> scores -> softmax -> PV
    //      -> proj2 -> ln -> MLP1 -> MLP2 ----
    for (int half = 0; half < 2; half++) {
        cudaStream_t sc_ = half ? s1 : s0;
        const long long bo = (long long)half * 2;       // batch offset
        const long long ro = bo * TQ;                   // row offset

        // flash self-attention (this half's 2 batches)
        flash_self<<<dim3(TQ/128, 2*HH), 256, SMFL, sc_>>>(
            qkvh + ro*3*DM, qkvl + ro*3*DM, de_mask + bo*SK,
            ctxh + ro*DM, ctxl + ro*DM);

        // proj1: x = dec_in + ctx @ w_out1^T + b_out1
        gemm_t2<0,true,true><<<dim3(DM/128, (BT/2)/128, 1), 256, SM_T2, sc_>>>(
            ctxh + ro*DM, ctxl + ro*DM, DM, 0, 0,  wo1h, wo1l, DM, 0, 0,
            x + ro*DM, xh + ro*DM, xl + ro*DM, DM, 0, 0,
            b_out1, dec_in + ro*DM, DM, DM, 1.0f, 1);

        // q2
        gemm_t2<0,false,true><<<dim3(DM/128, (BT/2)/128, 1), 256, SM_T2, sc_>>>(
            xh + ro*DM, xl + ro*DM, DM, 0, 0,  w2h, w2l, DM, 0, 0,
            nullptr, q2h + ro*DM, q2l + ro*DM, DM, 0, 0,
            b_in2, nullptr, 0, DM, 1.0f, 1);

        // s0 needs kv2/tvn from s1 before scores (s1 has them in-order)
        if (half == 0) cudaStreamWaitEvent(s0, g_evSide, 0);

        // cross scores
        gemm_t2<0,true,false><<<dim3(SK/128, TQ/128, 2*HH), 256, SM_T2, sc_>>>(
            q2h + ro*DM, q2l + ro*DM, DM, (long long)TQ*DM, HD,
            kv2h + bo*SK*2*DM, kv2l + bo*SK*2*DM, 2*DM, (long long)SK*2*DM, HD,
            scores + bo*TSb, nullptr, nullptr, SK, TSb, TSh,
            nullptr, nullptr, 0, HD, 0.125f, HH);

        // fused softmax + out2
        softmax_fused<<<dim3(TQ/8, 2), 256, 0, sc_>>>(
            scores + bo*TSb, en_mask + bo*SK, tvn + bo*SK,
            ph + bo*TSb, pl + bo*TSb, out2 + ro*SK);

        // PV
        gemm_t2n<64,false,true><<<dim3(1, TQ/128, 2*HH), 256, SM_T2N64, sc_>>>(
            ph + bo*TSb, pl + bo*TSb, SK, TSb, TSh,
            kv2h + DM + bo*SK*2*DM, kv2l + DM + bo*SK*2*DM, 2*DM, (long long)SK*2*DM, HD,
            nullptr, ctxh + ro*DM, ctxl + ro*DM, DM, (long long)TQ*DM, HD,
            nullptr, nullptr, 0, SK, 1.0f, HH);

        // proj2: x2 = x + ctx @ w_out2^T + b_out2
        gemm_t2<0,true,false><<<dim3(DM/128, (BT/2)/128, 1), 256, SM_T2, sc_>>>(
            ctxh + ro*DM, ctxl + ro*DM, DM, 0, 0,  wo2h, wo2l, DM, 0, 0,
            x2 + ro*DM, nullptr, nullptr, DM, 0, 0,
            b_out2, x + ro*DM, DM, DM, 1.0f, 1);

        // lnx
        ln_split<<<BT/2, 256, 0, sc_>>>(x2 + ro*DM, lnxh + ro*DM, lnxl + ro*DM, ln_g, ln_b);

        // MLP1
        gemm_t2<1,false,true><<<dim3(4*DM/128, (BT/2)/128, 1), 256, SM_T2, sc_>>>(
            lnxh + ro*DM, lnxl + ro*DM, DM, 0, 0,  m1h, m1l, DM, 0, 0,
            nullptr, hhp + ro*4*DM, hlp + ro*4*DM, 4*DM, 0, 0,
            mlp_b1, nullptr, 0, DM, 1.0f, 1);

        // MLP2
        gemm_t2<0,true,false><<<dim3(DM/128, (BT/2)/128, 1), 256, SM_T2, sc_>>>(
            hhp + ro*4*DM, hlp + ro*4*DM, 4*DM, 0, 0,  m2h, m2l, 4*DM, 0, 0,
            out1 + ro*DM, nullptr, nullptr, DM, 0, 0,
            mlp_b2, x2 + ro*DM, DM, 4*DM, 1.0f, 1);
    }

    // join: graph end must include s1's chain
    cudaEventRecord(g_evS1d, s1);
    cudaStreamWaitEvent(s0, g_evS1d, 0);
}

// round 17
// speedup vs baseline: 1.0202x; 1.0202x over previous
#include <cuda_runtime.h>
#include <cuda_bf16.h>
#include <math.h>
#include <stdint.h>

#define BZ 4
#define TQ 1024
#define SK 1024
#define DM 1024
#define HH 16
#define HD 64

typedef unsigned short u16;
typedef uint32_t u32;

// ---------------------------------------------------------------------------
// Scratch (fp32)
// ---------------------------------------------------------------------------
__device__ float g_scores[(long long)BZ * HH * TQ * SK];
__device__ float g_x   [BZ * TQ * DM];
__device__ float g_x2  [BZ * TQ * DM];
__device__ float g_tv  [BZ * SK * DM];
__device__ float g_tvn [BZ * SK];

// ---------------------------------------------------------------------------
// Scratch (bf16 hi/lo split pairs)
// ---------------------------------------------------------------------------
__device__ u16 g_deh[BZ*TQ*DM],    g_del[BZ*TQ*DM];
__device__ u16 g_enh[BZ*SK*DM],    g_enl[BZ*SK*DM];
__device__ u16 g_qkvh[BZ*TQ*3*DM], g_qkvl[BZ*TQ*3*DM];
__device__ u16 g_ctxh[BZ*TQ*DM],   g_ctxl[BZ*TQ*DM];
__device__ u16 g_xh[BZ*TQ*DM],     g_xl[BZ*TQ*DM];
__device__ u16 g_q2h[BZ*TQ*DM],    g_q2l[BZ*TQ*DM];
__device__ u16 g_kv2h[BZ*SK*2*DM], g_kv2l[BZ*SK*2*DM];
__device__ u16 g_lnxh[BZ*TQ*DM],   g_lnxl[BZ*TQ*DM];
__device__ u16 g_hh[BZ*TQ*4*DM],   g_hl[BZ*TQ*4*DM];
__device__ u16 g_ph[(long long)BZ*HH*TQ*SK], g_pl[(long long)BZ*HH*TQ*SK];
// weights
__device__ u16 g_w1h[3*DM*DM],  g_w1l[3*DM*DM];
__device__ u16 g_wo1h[DM*DM],   g_wo1l[DM*DM];
__device__ u16 g_w2h[3*DM*DM],  g_w2l[3*DM*DM];
__device__ u16 g_wo2h[DM*DM],   g_wo2l[DM*DM];
__device__ u16 g_m1h[4*DM*DM],  g_m1l[4*DM*DM];
__device__ u16 g_m2h[4*DM*DM],  g_m2l[4*DM*DM];

// ---------------------------------------------------------------------------
// Streams / events
// ---------------------------------------------------------------------------
static cudaStream_t g_s1;
static cudaEvent_t  g_evRoot, g_evW1, g_evSplit, g_evSide, g_evMW, g_evQ2, g_evS1d;
static bool g_stream_init = []() {
    cudaStreamCreateWithFlags(&g_s1, cudaStreamNonBlocking);
    cudaEventCreateWithFlags(&g_evRoot,  cudaEventDisableTiming);
    cudaEventCreateWithFlags(&g_evW1,    cudaEventDisableTiming);
    cudaEventCreateWithFlags(&g_evSplit, cudaEventDisableTiming);
    cudaEventCreateWithFlags(&g_evSide,  cudaEventDisableTiming);
    cudaEventCreateWithFlags(&g_evMW,    cudaEventDisableTiming);
    cudaEventCreateWithFlags(&g_evQ2,    cudaEventDisableTiming);
    cudaEventCreateWithFlags(&g_evS1d,   cudaEventDisableTiming);
    return true;
}();

// ---------------------------------------------------------------------------
// Primitives
// ---------------------------------------------------------------------------
__device__ __forceinline__ u32 smem_u32(const void* p) {
    u32 a;
    asm("{ .reg .u64 t; cvta.to.shared.u64 t, %1; cvt.u32.u64 %0, t; }" : "=r"(a) : "l"(p));
    return a;
}
__device__ __forceinline__ void ldsm_x4(u32 addr, u32* r) {
    asm volatile("ldmatrix.sync.aligned.m8n8.x4.shared.b16 {%0,%1,%2,%3}, [%4];"
        : "=r"(r[0]), "=r"(r[1]), "=r"(r[2]), "=r"(r[3]) : "r"(addr));
}
__device__ __forceinline__ void ldsm_x4_t(u32 addr, u32* r) {
    asm volatile("ldmatrix.sync.aligned.m8n8.x4.trans.shared.b16 {%0,%1,%2,%3}, [%4];"
        : "=r"(r[0]), "=r"(r[1]), "=r"(r[2]), "=r"(r[3]) : "r"(addr));
}
__device__ __forceinline__ void mma_bf16(float* c, const u32* a, const u32* b) {
    asm volatile("mma.sync.aligned.m16n8k16.row.col.f32.bf16.bf16.f32 "
        "{%0,%1,%2,%3}, {%4,%5,%6,%7}, {%8,%9}, {%0,%1,%2,%3};"
        : "+f"(c[0]), "+f"(c[1]), "+f"(c[2]), "+f"(c[3])
        : "r"(a[0]), "r"(a[1]), "r"(a[2]), "r"(a[3]), "r"(b[0]), "r"(b[1]));
}
#define CP_ASYNC16(dst, src) \
    asm volatile("cp.async.cg.shared.global [%0], [%1], 16;" :: "r"(dst), "l"(src))
#define CP_COMMIT() asm volatile("cp.async.commit_group;" ::: "memory")
#define CP_WAIT(n)  asm volatile("cp.async.wait_group %0;" :: "n"(n) : "memory")

__device__ __forceinline__ void split_bf16(float f, u16& h, u16& l) {
    __nv_bfloat16 bh = __float2bfloat16(f);
    float fl = f - __bfloat162float(bh);
    h = __bfloat16_as_ushort(bh);
    l = __bfloat16_as_ushort(__float2bfloat16(fl));
}
__device__ __forceinline__ u32 packhi2(float a, float b) {
    __nv_bfloat162 t = __floats2bfloat162_rn(a, b);
    return *reinterpret_cast<u32*>(&t);
}
__device__ __forceinline__ u32 packlo2(float a, float b) {
    float la = a - __bfloat162float(__float2bfloat16(a));
    float lb = b - __bfloat162float(__float2bfloat16(b));
    return packhi2(la, lb);
}

// ---------------------------------------------------------------------------
// Elementwise split
// ---------------------------------------------------------------------------
__global__ __launch_bounds__(256)
void split_kernel(const float* __restrict__ src, u16* __restrict__ hi,
                  u16* __restrict__ lo, int n4)
{
    int i = blockIdx.x * 256 + threadIdx.x;
    if (i >= n4) return;
    float4 v = ((const float4*)src)[i];
    u16 h0,h1,h2,h3,l0,l1,l2,l3;
    split_bf16(v.x,h0,l0); split_bf16(v.y,h1,l1);
    split_bf16(v.z,h2,l2); split_bf16(v.w,h3,l3);
    ((uint2*)hi)[i] = make_uint2((u32)h0 | ((u32)h1 << 16), (u32)h2 | ((u32)h3 << 16));
    ((uint2*)lo)[i] = make_uint2((u32)l0 | ((u32)l1 << 16), (u32)l2 | ((u32)l3 << 16));
}

// ---------------------------------------------------------------------------
// Reductions
// ---------------------------------------------------------------------------
__device__ __forceinline__ float block_sum(float v, float* sh) {
#pragma unroll
    for (int o = 16; o > 0; o >>= 1) v += __shfl_xor_sync(0xffffffffu, v, o);
    if ((threadIdx.x & 31) == 0) sh[threadIdx.x >> 5] = v;
    __syncthreads();
    if (threadIdx.x < 32) {
        float w = (threadIdx.x < 8) ? sh[threadIdx.x] : 0.0f;
#pragma unroll
        for (int o = 4; o > 0; o >>= 1) w += __shfl_xor_sync(0xffffffffu, w, o);
        if (threadIdx.x == 0) sh[0] = w;
    }
    __syncthreads();
    float r = sh[0];
    __syncthreads();
    return r;
}

// ---------------------------------------------------------------------------
// LayerNorm emitting split bf16
// ---------------------------------------------------------------------------
__global__ __launch_bounds__(256)
void ln_split(const float* __restrict__ x, u16* __restrict__ yh, u16* __restrict__ yl,
              const float* __restrict__ g, const float* __restrict__ beta)
{
    __shared__ float sh[32];
    const long long row = blockIdx.x;
    const float* xr = x + row * DM;
    const int tid = threadIdx.x;
    float v[4];
    float s = 0.f, sq = 0.f;
#pragma unroll
    for (int i = 0; i < 4; i++) {
        float t = xr[tid + 256 * i];
        v[i] = t; s += t; sq += t * t;
    }
    s  = block_sum(s, sh);
    sq = block_sum(sq, sh);
    float mean = s * (1.0f / 1024.0f);
    float var  = fmaxf(sq * (1.0f / 1024.0f) - mean * mean, 0.0f);
    float inv  = rsqrtf(var + 1e-6f);
#pragma unroll
    for (int i = 0; i < 4; i++) {
        int c = tid + 256 * i;
        float y = (v[i] - mean) * inv * g[c] + beta[c];
        u16 h, l;
        split_bf16(y, h, l);
        yh[row * DM + c] = h;
        yl[row * DM + c] = l;
    }
}

// ---------------------------------------------------------------------------
// GEMM t2 (TRANSB, BN=128): 256 threads, 8 warps (2m x 4n), warp 64x32,
// S=2 double buffer, 2 CTAs/SM.
// ---------------------------------------------------------------------------
template<int ACT, bool EF32, bool ESPL>
__global__ __launch_bounds__(256, 2)
void gemm_t2(const u16* __restrict__ Ahg, const u16* __restrict__ Alg, int lda,
             long long Ab, long long Aho,
             const u16* __restrict__ Bhg, const u16* __restrict__ Blg, int ldb,
             long long Bb, long long Bho,
             float* __restrict__ Cf, u16* __restrict__ Chg, u16* __restrict__ Clg,
             int ldc, long long Cb, long long Cho,
             const float* __restrict__ bias,
             const float* __restrict__ res, int ldr,
             int K, float alpha, int nh)
{
    constexpr int PA = 40;
    constexpr int ASZ = 128 * PA;
    constexpr int BSZ = 128 * PA;
    constexpr int STAGE = 2 * ASZ + 2 * BSZ;

    extern __shared__ __align__(128) u16 sm[];

    const int tid = threadIdx.x;
    const int lane = tid & 31;
    const int wid = tid >> 5;
    const int wm = (wid & 1) * 64;
    const int wn = (wid >> 1) * 32;

    const int bz = blockIdx.z;
    const int bb = bz / nh;
    const int hh = bz - bb * nh;
    const int m0 = blockIdx.y * 128;
    const int n0 = blockIdx.x * 128;

    const u16* Ah = Ahg + bb * Ab + hh * Aho + (long long)m0 * lda;
    const u16* Al = Alg + bb * Ab + hh * Aho + (long long)m0 * lda;
    const u16* Bh = Bhg + bb * Bb + hh * Bho + (long long)n0 * ldb;
    const u16* Bl = Blg + bb * Bb + hh * Bho + (long long)n0 * ldb;

    float acc[4][4][4];
#pragma unroll
    for (int mi = 0; mi < 4; mi++)
#pragma unroll
        for (int ni = 0; ni < 4; ni++)
#pragma unroll
            for (int j = 0; j < 4; j++) acc[mi][ni][j] = 0.0f;

    const u32 sb0 = smem_u32(sm);
    const int nk = K >> 5;

    auto issue = [&](int k) {
        const int slot = k & 1;
        const int k0 = k << 5;
        const u32 st = sb0 + (u32)(slot * STAGE) * 2;
#pragma unroll
        for (int u = 0; u < 2; u++) {
            const int idx = tid + u * 256;
            const int row = idx >> 2, c = idx & 3;
            const long long oa = (long long)row * lda + k0 + c * 8;
            const long long ob = (long long)row * ldb + k0 + c * 8;
            const u32 da = st + (u32)(row * PA + c * 8) * 2;
            CP_ASYNC16(da, (const void*)(Ah + oa));
            CP_ASYNC16(da + (u32)ASZ * 2, (const void*)(Al + oa));
            CP_ASYNC16(da + (u32)ASZ * 4, (const void*)(Bh + ob));
            CP_ASYNC16(da + (u32)ASZ * 4 + (u32)BSZ * 2, (const void*)(Bl + ob));
        }
    };

    issue(0);
    CP_COMMIT();

    for (int k = 0; k < nk; k++) {
        CP_WAIT(0);
        __syncthreads();
        if (k + 1 < nk) issue(k + 1);
        CP_COMMIT();

        const u32 base = sb0 + (u32)((k & 1) * STAGE) * 2;
#pragma unroll
        for (int kk = 0; kk < 32; kk += 16) {
            u32 bh_[4][2], bl_[4][2];
            {
                const int brow = wn + (lane & 7) + ((lane & 16) >> 1);
                const int bcol = kk + (((lane >> 3) & 1) << 3);
#pragma unroll
                for (int nj = 0; nj < 2; nj++) {
                    u32 bd = base + (u32)(2 * ASZ + (brow + nj * 16) * PA + bcol) * 2;
                    u32 r[4];
                    ldsm_x4(bd, r);
                    bh_[2*nj][0]=r[0]; bh_[2*nj][1]=r[1];
                    bh_[2*nj+1][0]=r[2]; bh_[2*nj+1][1]=r[3];
                    ldsm_x4(bd + (u32)BSZ * 2, r);
                    bl_[2*nj][0]=r[0]; bl_[2*nj][1]=r[1];
                    bl_[2*nj+1][0]=r[2]; bl_[2*nj+1][1]=r[3];
                }
            }
            const int arow = wm + (lane & 15);
            const int acol = kk + ((lane >> 4) << 3);
#pragma unroll
            for (int mi = 0; mi < 4; mi++) {
                u32 ah[4], al_[4];
                u32 ad = base + (u32)(((arow + mi * 16) * PA) + acol) * 2;
                ldsm_x4(ad, ah);
                ldsm_x4(ad + (u32)ASZ * 2, al_);
#pragma unroll
                for (int ni = 0; ni < 4; ni++) {
                    mma_bf16(acc[mi][ni], ah, bh_[ni]);
                    mma_bf16(acc[mi][ni], ah, bl_[ni]);
                    mma_bf16(acc[mi][ni], al_, bh_[ni]);
                }
            }
        }
    }

    float* Cfg = EF32 ? (Cf + bb * Cb + hh * Cho) : nullptr;
    u16* Chh = ESPL ? (Chg + bb * Cb + hh * Cho) : nullptr;
    u16* Cll = ESPL ? (Clg + bb * Cb + hh * Cho) : nullptr;
#pragma unroll
    for (int mi = 0; mi < 4; mi++) {
#pragma unroll
        for (int ni = 0; ni < 4; ni++) {
            int m = m0 + wm + mi * 16 + (lane >> 2);
            int n = n0 + wn + ni * 8 + (lane & 3) * 2;
#pragma unroll
            for (int rr = 0; rr < 2; rr++) {
                int mm = m + rr * 8;
                float v0 = acc[mi][ni][rr * 2 + 0] * alpha;
                float v1 = acc[mi][ni][rr * 2 + 1] * alpha;
                if (bias) { v0 += bias[n]; v1 += bias[n + 1]; }
                if (ACT == 1) {
                    v0 = 0.5f * v0 * (1.0f + erff(v0 * 0.70710678118654752f));
                    v1 = 0.5f * v1 * (1.0f + erff(v1 * 0.70710678118654752f));
                }
                if (res) {
                    v0 += res[(long long)mm * ldr + n];
                    v1 += res[(long long)mm * ldr + n + 1];
                }
                long long co = (long long)mm * ldc + n;
                if (EF32) *(float2*)(Cfg + co) = make_float2(v0, v1);
                if (ESPL) {
                    *(u32*)(Chh + co) = packhi2(v0, v1);
                    *(u32*)(Cll + co) = packlo2(v0, v1);
                }
            }
        }
    }
}

// ---------------------------------------------------------------------------
// GEMM t2n (non-TRANSB): B[K,N] staged [32][BN+8] + ldsm.trans. S=2.
// ---------------------------------------------------------------------------
template<int BN, bool EF32, bool ESPL>
__global__ __launch_bounds__(256, 2)
void gemm_t2n(const u16* __restrict__ Ahg, const u16* __restrict__ Alg, int lda,
              long long Ab, long long Aho,
              const u16* __restrict__ Bhg, const u16* __restrict__ Blg, int ldb,
              long long Bb, long long Bho,
              float* __restrict__ Cf, u16* __restrict__ Chg, u16* __restrict__ Clg,
              int ldc, long long Cb, long long Cho,
              const float* __restrict__ bias,
              const float* __restrict__ res, int ldr,
              int K, float alpha, int nh)
{
    constexpr int PA = 40;
    constexpr int ASZ = 128 * PA;
    constexpr int PB = BN + 8;
    constexpr int BSZ = 32 * PB;
    constexpr int STAGE = 2 * ASZ + 2 * BSZ;
    constexpr int WN = BN / 4;
    constexpr int NT = WN / 8;

    extern __shared__ __align__(128) u16 sm[];

    const int tid = threadIdx.x;
    const int lane = tid & 31;
    const int wid = tid >> 5;
    const int wm = (wid & 1) * 64;
    const int wn = (wid >> 1) * WN;

    const int bz = blockIdx.z;
    const int bb = bz / nh;
    const int hh = bz - bb * nh;
    const int m0 = blockIdx.y * 128;
    const int n0 = blockIdx.x * BN;

    const u16* Ah = Ahg + bb * Ab + hh * Aho + (long long)m0 * lda;
    const u16* Al = Alg + bb * Ab + hh * Aho + (long long)m0 * lda;
    const u16* Bh = Bhg + bb * Bb + hh * Bho + (long long)n0;
    const u16* Bl = Blg + bb * Bb + hh * Bho + (long long)n0;

    float acc[4][NT][4];
#pragma unroll
    for (int mi = 0; mi < 4; mi++)
#pragma unroll
        for (int ni = 0; ni < NT; ni++)
#pragma unroll
            for (int j = 0; j < 4; j++) acc[mi][ni][j] = 0.0f;

    const u32 sb0 = smem_u32(sm);
    const int nk = K >> 5;

    auto issue = [&](int k) {
        const int slot = k & 1;
        const int k0 = k << 5;
        const u32 st = sb0 + (u32)(slot * STAGE) * 2;
#pragma unroll
        for (int u = 0; u < 2; u++) {
            const int idx = tid + u * 256;
            const int row = idx >> 2, c = idx & 3;
            const long long oa = (long long)row * lda + k0 + c * 8;
            const u32 da = st + (u32)(row * PA + c * 8) * 2;
            CP_ASYNC16(da, (const void*)(Ah + oa));
            CP_ASYNC16(da + (u32)ASZ * 2, (const void*)(Al + oa));
        }
#pragma unroll
        for (int u = 0; u < BN / 64; u++) {
            const int idx = tid + u * 256;
            const int row = (BN == 128) ? (idx >> 4) : (idx >> 3);
            const int c   = (BN == 128) ? (idx & 15) : (idx & 7);
            const long long o = (long long)(k0 + row) * ldb + c * 8;
            const u32 d = st + (u32)(2 * ASZ + row * PB + c * 8) * 2;
            CP_ASYNC16(d, (const void*)(Bh + o));
            CP_ASYNC16(d + (u32)BSZ * 2, (const void*)(Bl + o));
        }
    };

    issue(0);
    CP_COMMIT();

    for (int k = 0; k < nk; k++) {
        CP_WAIT(0);
        __syncthreads();
        if (k + 1 < nk) issue(k + 1);
        CP_COMMIT();

        const u32 base = sb0 + (u32)((k & 1) * STAGE) * 2;
#pragma unroll
        for (int kk = 0; kk < 32; kk += 16) {
            u32 bh_[NT][2], bl_[NT][2];
            {
                const int brow = kk + (lane & 15);
#pragma unroll
                for (int nj = 0; nj < NT / 2; nj++) {
                    const int bcol = wn + nj * 16 + ((lane >> 4) << 3);
                    u32 bd = base + (u32)(2 * ASZ + brow * PB + bcol) * 2;
                    u32 r[4];
                    ldsm_x4_t(bd, r);
                    bh_[2*nj][0]=r[0]; bh_[2*nj][1]=r[1];
                    bh_[2*nj+1][0]=r[2]; bh_[2*nj+1][1]=r[3];
                    ldsm_x4_t(bd + (u32)BSZ * 2, r);
                    bl_[2*nj][0]=r[0]; bl_[2*nj][1]=r[1];
                    bl_[2*nj+1][0]=r[2]; bl_[2*nj+1][1]=r[3];
                }
            }
            const int arow = wm + (lane & 15);
            const int acol = kk + ((lane >> 4) << 3);
#pragma unroll
            for (int mi = 0; mi < 4; mi++) {
                u32 ah[4], al_[4];
                u32 ad = base + (u32)(((arow + mi * 16) * PA) + acol) * 2;
                ldsm_x4(ad, ah);
                ldsm_x4(ad + (u32)ASZ * 2, al_);
#pragma unroll
                for (int ni = 0; ni < NT; ni++) {
                    mma_bf16(acc[mi][ni], ah, bh_[ni]);
                    mma_bf16(acc[mi][ni], ah, bl_[ni]);
                    mma_bf16(acc[mi][ni], al_, bh_[ni]);
                }
            }
        }
    }

    float* Cfg = EF32 ? (Cf + bb * Cb + hh * Cho) : nullptr;
    u16* Chh = ESPL ? (Chg + bb * Cb + hh * Cho) : nullptr;
    u16* Cll = ESPL ? (Clg + bb * Cb + hh * Cho) : nullptr;
#pragma unroll
    for (int mi = 0; mi < 4; mi++) {
#pragma unroll
        for (int ni = 0; ni < NT; ni++) {
            int m = m0 + wm + mi * 16 + (lane >> 2);
            int n = n0 + wn + ni * 8 + (lane & 3) * 2;
#pragma unroll
            for (int rr = 0; rr < 2; rr++) {
                int mm = m + rr * 8;
                float v0 = acc[mi][ni][rr * 2 + 0] * alpha;
                float v1 = acc[mi][ni][rr * 2 + 1] * alpha;
                if (bias) { v0 += bias[n]; v1 += bias[n + 1]; }
                if (res) {
                    v0 += res[(long long)mm * ldr + n];
                    v1 += res[(long long)mm * ldr + n + 1];
                }
                long long co = (long long)mm * ldc + n;
                if (EF32) *(float2*)(Cfg + co) = make_float2(v0, v1);
                if (ESPL) {
                    *(u32*)(Chh + co) = packhi2(v0, v1);
                    *(u32*)(Cll + co) = packlo2(v0, v1);
                }
            }
        }
    }
}

// ---------------------------------------------------------------------------
// Flash self-attention v2
// ---------------------------------------------------------------------------
__global__ __launch_bounds__(256)
void flash_self(const u16* __restrict__ qh, const u16* __restrict__ ql,
                const unsigned char* __restrict__ kpm,
                u16* __restrict__ ch, u16* __restrict__ cl)
{
    constexpr int P = 72;
    constexpr int TSZ = 64 * P;
    constexpr int QTSZ = 128 * P;
    extern __shared__ __align__(128) u16 fs[];
    unsigned char* smask = (unsigned char*)(fs + 2 * QTSZ + 8 * TSZ);

    const int tid = threadIdx.x, lane = tid & 31, wid = tid >> 5;
    const int bx = blockIdx.x;
    const int bh = blockIdx.y;
    const int b = bh >> 4, h = bh & 15;
    const int t0 = bx * 128;

    const long long qoff = ((long long)b * TQ + t0) * 3 * DM + h * HD;
    const long long koff = ((long long)b * TQ) * 3 * DM + DM + h * HD;
    const long long voff = ((long long)b * TQ) * 3 * DM + 2 * DM + h * HD;
    const unsigned char* kp = kpm + (long long)b * SK;

    const u32 fsb = smem_u32(fs);
    const u32 kvb0 = fsb + (u32)(2 * QTSZ) * 2;

    auto issueKV = [&](int ch_i, int bufi) {
        const int s0 = ch_i * 64;
        const u32 kvb = kvb0 + (u32)(bufi * 4 * TSZ) * 2;
#pragma unroll
        for (int u = 0; u < 2; u++) {
            int idx = tid + u * 256;
            int r = idx >> 3, c8 = idx & 7;
            long long ko = koff + (long long)(s0 + r) * 3 * DM + c8 * 8;
            long long vo = voff + (long long)(s0 + r) * 3 * DM + c8 * 8;
            u32 d = kvb + (u32)(r * P + c8 * 8) * 2;
            CP_ASYNC16(d,                (const void*)(qh + ko));
            CP_ASYNC16(d + (u32)TSZ * 2, (const void*)(ql + ko));
            CP_ASYNC16(d + (u32)TSZ * 4, (const void*)(qh + vo));
            CP_ASYNC16(d + (u32)TSZ * 6, (const void*)(ql + vo));
        }
    };

    issueKV(0, 0);
    CP_COMMIT();
#pragma unroll
    for (int u = 0; u < 4; u++) {
        int idx = tid + u * 256;
        int r = idx >> 3, c8 = idx & 7;
        long long o = qoff + (long long)r * 3 * DM + c8 * 8;
        int off = r * P + c8 * 8;
        *(uint4*)(fs + off)        = *(const uint4*)(qh + o);
        *(uint4*)(fs + QTSZ + off) = *(const uint4*)(ql + o);
    }
    if (tid < 64) smask[tid] = kp[tid];

    float o_[8][4];
#pragma unroll
    for (int i = 0; i < 8; i++)
#pragma unroll
        for (int j = 0; j < 4; j++) o_[i][j] = 0.0f;
    float mrow0 = -1e30f, mrow1 = -1e30f, lrow0 = 0.0f, lrow1 = 0.0f;

    const int warp_last_row = t0 + wid * 16 + 15;
    const int nch = 2 * (bx + 1);
    int buf = 0;
    for (int ch_i = 0; ch_i < nch; ch_i++) {
        const int s0 = ch_i * 64;
        CP_WAIT(0);
        __syncthreads();
        if (ch_i + 1 < nch) {
            issueKV(ch_i + 1, buf ^ 1);
            if (tid < 64) smask[(buf ^ 1) * 64 + tid] = kp[s0 + 64 + tid];
        }
        CP_COMMIT();

        if (s0 <= warp_last_row) {
            const u32 kb = kvb0 + (u32)(buf * 4 * TSZ) * 2;
            const u32 vb = kb + (u32)TSZ * 4;
            const unsigned char* mk = smask + buf * 64;

            float sc[8][4];
#pragma unroll
            for (int i = 0; i < 8; i++)
#pragma unroll
                for (int j = 0; j < 4; j++) sc[i][j] = 0.0f;

#pragma unroll
            for (int kt = 0; kt < 4; kt++) {
                u32 aq[4], al_[4];
                u32 ad = fsb + (u32)(((wid * 16 + (lane & 15)) * P + kt * 16 + ((lane >> 4) << 3))) * 2;
                ldsm_x4(ad, aq);
                ldsm_x4(ad + (u32)QTSZ * 2, al_);
                u32 bh_[8][2], bl_[8][2];
#pragma unroll
                for (int nj = 0; nj < 4; nj++) {
                    u32 bd = kb + (u32)(((nj * 16 + (lane & 7) + ((lane & 16) >> 1)) * P
                                        + kt * 16 + (((lane >> 3) & 1) << 3))) * 2;
                    u32 r[4];
                    ldsm_x4(bd, r);
                    bh_[2*nj][0]=r[0]; bh_[2*nj][1]=r[1]; bh_[2*nj+1][0]=r[2]; bh_[2*nj+1][1]=r[3];
                    ldsm_x4(bd + (u32)TSZ * 2, r);
                    bl_[2*nj][0]=r[0]; bl_[2*nj][1]=r[1]; bl_[2*nj+1][0]=r[2]; bl_[2*nj+1][1]=r[3];
                }
#pragma unroll
                for (int ni = 0; ni < 8; ni++) {
                    mma_bf16(sc[ni], aq, bh_[ni]);
                    mma_bf16(sc[ni], aq, bl_[ni]);
                    mma_bf16(sc[ni], al_, bh_[ni]);
                }
            }

            const int gr0 = t0 + wid * 16 + (lane >> 2);
#pragma unroll
            for (int ni = 0; ni < 8; ni++) {
#pragma unroll
                for (int j = 0; j < 4; j++) {
                    int rr = gr0 + ((j >> 1) << 3);
                    int cl_ = ni * 8 + (lane & 3) * 2 + (j & 1);
                    float xv = sc[ni][j] * 0.125f;
                    if (s0 + cl_ > rr) xv -= 1e9f;
                    if (mk[cl_]) xv = -1e9f;
                    sc[ni][j] = xv;
                }
            }

            float mc0 = -1e30f, mc1 = -1e30f;
#pragma unroll
            for (int ni = 0; ni < 8; ni++) {
                mc0 = fmaxf(mc0, fmaxf(sc[ni][0], sc[ni][1]));
                mc1 = fmaxf(mc1, fmaxf(sc[ni][2], sc[ni][3]));
            }
#pragma unroll
            for (int off = 1; off <= 2; off <<= 1) {
                mc0 = fmaxf(mc0, __shfl_xor_sync(0xffffffffu, mc0, off));
                mc1 = fmaxf(mc1, __shfl_xor_sync(0xffffffffu, mc1, off));
            }
            float mn0 = fmaxf(mrow0, mc0), mn1 = fmaxf(mrow1, mc1);
            float scale0 = __expf(mrow0 - mn0), scale1 = __expf(mrow1 - mn1);
            float ls0 = 0.0f, ls1 = 0.0f;
#pragma unroll
            for (int ni = 0; ni < 8; ni++) {
                sc[ni][0] = __expf(sc[ni][0] - mn0);
                sc[ni][1] = __expf(sc[ni][1] - mn0);
                sc[ni][2] = __expf(sc[ni][2] - mn1);
                sc[ni][3] = __expf(sc[ni][3] - mn1);
                ls0 += sc[ni][0] + sc[ni][1];
                ls1 += sc[ni][2] + sc[ni][3];
            }
#pragma unroll
            for (int off = 1; off <= 2; off <<= 1) {
                ls0 += __shfl_xor_sync(0xffffffffu, ls0, off);
                ls1 += __shfl_xor_sync(0xffffffffu, ls1, off);
            }
            lrow0 = lrow0 * scale0 + ls0;
            lrow1 = lrow1 * scale1 + ls1;
            mrow0 = mn0; mrow1 = mn1;
#pragma unroll
            for (int ni = 0; ni < 8; ni++) {
                o_[ni][0] *= scale0; o_[ni][1] *= scale0;
                o_[ni][2] *= scale1; o_[ni][3] *= scale1;
            }

#pragma unroll
            for (int kt = 0; kt < 4; kt++) {
                u32 ph[4], pl[4];
                ph[0] = packhi2(sc[2*kt][0],   sc[2*kt][1]);
                ph[1] = packhi2(sc[2*kt][2],   sc[2*kt][3]);
                ph[2] = packhi2(sc[2*kt+1][0], sc[2*kt+1][1]);
                ph[3] = packhi2(sc[2*kt+1][2], sc[2*kt+1][3]);
                pl[0] = packlo2(sc[2*kt][0],   sc[2*kt][1]);
                pl[1] = packlo2(sc[2*kt][2],   sc[2*kt][3]);
                pl[2] = packlo2(sc[2*kt+1][0], sc[2*kt+1][1]);
                pl[3] = packlo2(sc[2*kt+1][2], sc[2*kt+1][3]);

                u32 vh_[8][2], vl_[8][2];
#pragma unroll
                for (int nj = 0; nj < 4; nj++) {
                    u32 bd = vb + (u32)(((kt * 16 + (lane & 15)) * P
                                        + nj * 16 + ((lane >> 4) << 3))) * 2;
                    u32 r[4];
                    ldsm_x4_t(bd, r);
                    vh_[2*nj][0]=r[0]; vh_[2*nj][1]=r[1]; vh_[2*nj+1][0]=r[2]; vh_[2*nj+1][1]=r[3];
                    ldsm_x4_t(bd + (u32)TSZ * 2, r);
                    vl_[2*nj][0]=r[0]; vl_[2*nj][1]=r[1]; vl_[2*nj+1][0]=r[2]; vl_[2*nj+1][1]=r[3];
                }
#pragma unroll
                for (int ni = 0; ni < 8; ni++) {
                    mma_bf16(o_[ni], ph, vh_[ni]);
                    mma_bf16(o_[ni], ph, vl_[ni]);
                    mma_bf16(o_[ni], pl, vh_[ni]);
                }
            }
        }
        buf ^= 1;
    }

    float inv0 = 1.0f / fmaxf(lrow0, 1e-30f);
    float inv1 = 1.0f / fmaxf(lrow1, 1e-30f);
    const long long cbase = ((long long)b * TQ) * DM + h * HD;
    const int r0 = t0 + wid * 16 + (lane >> 2);
#pragma unroll
    for (int ni = 0; ni < 8; ni++) {
        int c = ni * 8 + (lane & 3) * 2;
        long long o0 = cbase + (long long)r0 * DM + c;
        long long o1 = cbase + (long long)(r0 + 8) * DM + c;
        *(u32*)(ch + o0) = packhi2(o_[ni][0] * inv0, o_[ni][1] * inv0);
        *(u32*)(cl + o0) = packlo2(o_[ni][0] * inv0, o_[ni][1] * inv0);
        *(u32*)(ch + o1) = packhi2(o_[ni][2] * inv1, o_[ni][3] * inv1);
        *(u32*)(cl + o1) = packlo2(o_[ni][2] * inv1, o_[ni][3] * inv1);
    }
}

// ---------------------------------------------------------------------------
// Fused cross softmax v2 (warp-per-row)
// ---------------------------------------------------------------------------
__global__ __launch_bounds__(256)
void softmax_fused(const float* __restrict__ sc, const unsigned char* __restrict__ kpm,
                   const float* __restrict__ tvn,
                   u16* __restrict__ ph, u16* __restrict__ pl, float* __restrict__ out2)
{
    __shared__ unsigned char km[SK];
    const int lane = threadIdx.x & 31, warp = threadIdx.x >> 5;
    const int t = blockIdx.x * 8 + warp;
    const int b = blockIdx.y;
    for (int i = threadIdx.x; i < SK; i += 256) km[i] = kpm[(long long)b * SK + i];
    __syncthreads();

    float psum[32];
#pragma unroll
    for (int i = 0; i < 32; i++) psum[i] = 0.0f;

    unsigned char mk[32];
#pragma unroll
    for (int j = 0; j < 8; j++) {
        int s0 = (lane + 32 * j) * 4;
#pragma unroll
        for (int c = 0; c < 4; c++) mk[4 * j + c] = km[s0 + c];
    }

    for (int h = 0; h < HH; h++) {
        const long long roff = (((long long)(b * HH + h)) * TQ + t) * SK;
        float v[32];
        float mx = -3.4e38f;
#pragma unroll
        for (int j = 0; j < 8; j++) {
            float4 v4 = *(const float4*)(sc + roff + (lane + 32 * j) * 4);
            v[4*j+0] = mk[4*j+0] ? -1e9f : v4.x;
            v[4*j+1] = mk[4*j+1] ? -1e9f : v4.y;
            v[4*j+2] = mk[4*j+2] ? -1e9f : v4.z;
            v[4*j+3] = mk[4*j+3] ? -1e9f : v4.w;
#pragma unroll
            for (int c = 0; c < 4; c++) mx = fmaxf(mx, v[4*j+c]);
        }
#pragma unroll
        for (int o = 16; o > 0; o >>= 1) mx = fmaxf(mx, __shfl_xor_sync(0xffffffffu, mx, o));
        float sum = 0.0f;
#pragma unroll
        for (int i = 0; i < 32; i++) {
            v[i] = __expf(v[i] - mx);
            sum += v[i];
        }
#pragma unroll
        for (int o = 16; o > 0; o >>= 1) sum += __shfl_xor_sync(0xffffffffu, sum, o);
        float inv = 1.0f / sum;
#pragma unroll
        for (int j = 0; j < 8; j++) {
            float p0 = v[4*j+0] * inv, p1 = v[4*j+1] * inv;
            float p2 = v[4*j+2] * inv, p3 = v[4*j+3] * inv;
            psum[4*j+0] += p0; psum[4*j+1] += p1;
            psum[4*j+2] += p2; psum[4*j+3] += p3;
            long long so = roff + (lane + 32 * j) * 4;
            *(uint2*)(ph + so) = make_uint2(packhi2(p0, p1), packhi2(p2, p3));
            *(uint2*)(pl + so) = make_uint2(packlo2(p0, p1), packlo2(p2, p3));
        }
    }

    const long long obase = ((long long)b * TQ + t) * SK;
    const float* tvb = tvn + b * SK;
#pragma unroll
    for (int j = 0; j < 8; j++) {
        int s0 = (lane + 32 * j) * 4;
        float4 tv4 = *(const float4*)(tvb + s0);
        float4 o4 = make_float4(psum[4*j+0] * (1.0f/16.0f) * tv4.x,
                                psum[4*j+1] * (1.0f/16.0f) * tv4.y,
                                psum[4*j+2] * (1.0f/16.0f) * tv4.z,
                                psum[4*j+3] * (1.0f/16.0f) * tv4.w);
        *(float4*)(out2 + obase + s0) = o4;
    }
}

// ---------------------------------------------------------------------------
// Row L2 norm
// ---------------------------------------------------------------------------
__global__ __launch_bounds__(256)
void rownorm_kernel(const float* __restrict__ x, float* __restrict__ out)
{
    __shared__ float sh[32];
    const long long row = blockIdx.x;
    const float* xr = x + row * DM;
    float sq = 0.f;
#pragma unroll
    for (int i = 0; i < 4; i++) {
        float t = xr[threadIdx.x + 256 * i];
        sq += t * t;
    }
    sq = block_sum(sq, sh);
    if (threadIdx.x == 0) out[row] = sqrtf(sq);
}

// ---------------------------------------------------------------------------
// Host launcher — R15 schedule + deferred MLP weight splits
// ---------------------------------------------------------------------------
extern "C" void kernel_launch(void* const* d_in, const int* in_sizes, int n_in,
                              void* d_out, int out_size)
{
    const float* dec_in  = (const float*)d_in[0];
    const float* enc_out = (const float*)d_in[1];
    const unsigned char* en_mask = (const unsigned char*)d_in[2];
    const unsigned char* de_mask = (const unsigned char*)d_in[3];
    const float* ln_g   = (const float*)d_in[4];
    const float* ln_b   = (const float*)d_in[5];
    const float* w_in1  = (const float*)d_in[6];
    const float* b_in1  = (const float*)d_in[7];
    const float* w_out1 = (const float*)d_in[8];
    const float* b_out1 = (const float*)d_in[9];
    const float* w_in2  = (const float*)d_in[10];
    const float* b_in2  = (const float*)d_in[11];
    const float* w_out2 = (const float*)d_in[12];
    const float* b_out2 = (const float*)d_in[13];
    const float* mlp_w1 = (const float*)d_in[14];
    const float* mlp_b1 = (const float*)d_in[15];
    const float* mlp_w2 = (const float*)d_in[16];
    const float* mlp_b2 = (const float*)d_in[17];

    float *scores, *x, *x2, *tv, *tvn;
    cudaGetSymbolAddress((void**)&scores, g_scores);
    cudaGetSymbolAddress((void**)&x,  g_x);
    cudaGetSymbolAddress((void**)&x2, g_x2);
    cudaGetSymbolAddress((void**)&tv, g_tv);
    cudaGetSymbolAddress((void**)&tvn, g_tvn);

    u16 *deh,*del,*enh,*enl,*qkvh,*qkvl,*ctxh,*ctxl,*xh,*xl,*q2h,*q2l,*kv2h,*kv2l;
    u16 *lnxh,*lnxl,*hhp,*hlp,*ph,*pl;
    u16 *w1h,*w1l,*wo1h,*wo1l,*w2h,*w2l,*wo2h,*wo2l,*m1h,*m1l,*m2h,*m2l;
    cudaGetSymbolAddress((void**)&deh, g_deh);   cudaGetSymbolAddress((void**)&del, g_del);
    cudaGetSymbolAddress((void**)&enh, g_enh);   cudaGetSymbolAddress((void**)&enl, g_enl);
    cudaGetSymbolAddress((void**)&qkvh, g_qkvh); cudaGetSymbolAddress((void**)&qkvl, g_qkvl);
    cudaGetSymbolAddress((void**)&ctxh, g_ctxh); cudaGetSymbolAddress((void**)&ctxl, g_ctxl);
    cudaGetSymbolAddress((void**)&xh, g_xh);     cudaGetSymbolAddress((void**)&xl, g_xl);
    cudaGetSymbolAddress((void**)&q2h, g_q2h);   cudaGetSymbolAddress((void**)&q2l, g_q2l);
    cudaGetSymbolAddress((void**)&kv2h, g_kv2h); cudaGetSymbolAddress((void**)&kv2l, g_kv2l);
    cudaGetSymbolAddress((void**)&lnxh, g_lnxh); cudaGetSymbolAddress((void**)&lnxl, g_lnxl);
    cudaGetSymbolAddress((void**)&hhp, g_hh);    cudaGetSymbolAddress((void**)&hlp, g_hl);
    cudaGetSymbolAddress((void**)&ph, g_ph);     cudaGetSymbolAddress((void**)&pl, g_pl);
    cudaGetSymbolAddress((void**)&w1h, g_w1h);   cudaGetSymbolAddress((void**)&w1l, g_w1l);
    cudaGetSymbolAddress((void**)&wo1h, g_wo1h); cudaGetSymbolAddress((void**)&wo1l, g_wo1l);
    cudaGetSymbolAddress((void**)&w2h, g_w2h);   cudaGetSymbolAddress((void**)&w2l, g_w2l);
    cudaGetSymbolAddress((void**)&wo2h, g_wo2h); cudaGetSymbolAddress((void**)&wo2l, g_wo2l);
    cudaGetSymbolAddress((void**)&m1h, g_m1h);   cudaGetSymbolAddress((void**)&m1l, g_m1l);
    cudaGetSymbolAddress((void**)&m2h, g_m2h);   cudaGetSymbolAddress((void**)&m2l, g_m2l);

    float* out1 = (float*)d_out;
    float* out2 = (float*)d_out + (long long)BZ * TQ * DM;

    const int BT = BZ * TQ;
    const long long TSh = (long long)TQ * SK;
    const long long TSb = (long long)HH * TQ * SK;

    const int SM_T2   = 2 * (4 * 128 * 40) * 2;                    //  81920
    const int SM_T2N128 = 2 * (2 * 128 * 40 + 2 * 32 * 136) * 2;   //  75776
    const int SM_T2N64  = 2 * (2 * 128 * 40 + 2 * 32 * 72)  * 2;   //  59392
    const int SMFL    = (2 * 128 * 72 + 8 * 64 * 72) * 2 + 128;    // 110720
    cudaFuncSetAttribute(gemm_t2<0,false,true >, cudaFuncAttributeMaxDynamicSharedMemorySize, SM_T2);
    cudaFuncSetAttribute(gemm_t2<0,true ,true >, cudaFuncAttributeMaxDynamicSharedMemorySize, SM_T2);
    cudaFuncSetAttribute(gemm_t2<0,true ,false>, cudaFuncAttributeMaxDynamicSharedMemorySize, SM_T2);
    cudaFuncSetAttribute(gemm_t2<1,false,true >, cudaFuncAttributeMaxDynamicSharedMemorySize, SM_T2);
    cudaFuncSetAttribute(gemm_t2n<128,true ,false>, cudaFuncAttributeMaxDynamicSharedMemorySize, SM_T2N128);
    cudaFuncSetAttribute(gemm_t2n<64 ,false,true >, cudaFuncAttributeMaxDynamicSharedMemorySize, SM_T2N64);
    cudaFuncSetAttribute(flash_self, cudaFuncAttributeMaxDynamicSharedMemorySize, SMFL);

    cudaStream_t s0 = 0;
    cudaStream_t s1 = g_s1;

    cudaEventRecord(g_evRoot, s0);
    cudaStreamWaitEvent(s1, g_evRoot, 0);

    // ---- side stream: w1 split first (feeds s0 QKV), then wo1/w2/wo2 ----
    split_kernel<<<(3*DM*DM/4 + 255)/256, 256, 0, s1>>>(w_in1, w1h, w1l, 3*DM*DM/4);
    cudaEventRecord(g_evW1, s1);
    split_kernel<<<(DM*DM/4   + 255)/256, 256, 0, s1>>>(w_out1, wo1h, wo1l, DM*DM/4);
    split_kernel<<<(3*DM*DM/4 + 255)/256, 256, 0, s1>>>(w_in2,  w2h,  w2l,  3*DM*DM/4);
    split_kernel<<<(DM*DM/4   + 255)/256, 256, 0, s1>>>(w_out2, wo2h, wo2l, DM*DM/4);
    cudaEventRecord(g_evSplit, s1);

    // encoder chain (kv2/tv need w2/wo2, in-order on s1)
    ln_split<<<BT, 256, 0, s1>>>(enc_out, enh, enl, ln_g, ln_b);
    gemm_t2<0,false,true><<<dim3(2*DM/128, BT/128, 1), 256, SM_T2, s1>>>(
        enh, enl, DM, 0, 0,  w2h + (long long)DM*DM, w2l + (long long)DM*DM, DM, 0, 0,
        nullptr, kv2h, kv2l, 2*DM, 0, 0,
        b_in2 + DM, nullptr, 0, DM, 1.0f, 1);
    gemm_t2n<128,true,false><<<dim3(DM/128, BT/128, 1), 256, SM_T2N128, s1>>>(
        enh, enl, DM, 0, 0,  wo2h, wo2l, DM, 0, 0,
        tv, nullptr, nullptr, DM, 0, 0,
        nullptr, nullptr, 0, DM, 1.0f, 1);
    rownorm_kernel<<<BT, 256, 0, s1>>>(tv, tvn);
    cudaEventRecord(g_evSide, s1);

    // deferred MLP weight splits (needed ~1 ms later)
    split_kernel<<<(4*DM*DM/4 + 255)/256, 256, 0, s1>>>(mlp_w1, m1h, m1l, 4*DM*DM/4);
    split_kernel<<<(4*DM*DM/4 + 255)/256, 256, 0, s1>>>(mlp_w2, m2h, m2l, 4*DM*DM/4);
    cudaEventRecord(g_evMW, s1);

    // ---- main stream: decoder branch (full batch head) ----
    ln_split<<<BT, 256, 0, s0>>>(dec_in, deh, del, ln_g, ln_b);
    cudaStreamWaitEvent(s0, g_evW1, 0);

    gemm_t2<0,false,true><<<dim3(3*DM/128, BT/128, 1), 256, SM_T2, s0>>>(
        deh, del, DM, 0, 0,  w1h, w1l, DM, 0, 0,
        nullptr, qkvh, qkvl, 3*DM, 0, 0,
        b_in1, nullptr, 0, DM, 1.0f, 1);

    flash_self<<<dim3(TQ/128, BZ*HH), 256, SMFL, s0>>>(qkvh, qkvl, de_mask, ctxh, ctxl);

    cudaStreamWaitEvent(s0, g_evSplit, 0);

    gemm_t2<0,true,true><<<dim3(DM/128, BT/128, 1), 256, SM_T2, s0>>>(
        ctxh, ctxl, DM, 0, 0,  wo1h, wo1l, DM, 0, 0,
        x, xh, xl, DM, 0, 0,
        b_out1, dec_in, DM, DM, 1.0f, 1);

    gemm_t2<0,false,true><<<dim3(DM/128, BT/128, 1), 256, SM_T2, s0>>>(
        xh, xl, DM, 0, 0,  w2h, w2l, DM, 0, 0,
        nullptr, q2h, q2l, DM, 0, 0,
        b_in2, nullptr, 0, DM, 1.0f, 1);

    // fork by batch half: b={0,1} on s0, b={2,3} on s1, through END of network
    cudaEventRecord(g_evQ2, s0);
    cudaStreamWaitEvent(s1, g_evQ2, 0);   // s1 half needs q2 (+ x)
    cudaStreamWaitEvent(s0, g_evSide, 0); // s0 half needs kv2/tvn
    cudaStreamWaitEvent(s0, g_evMW, 0);   // s0 half's MLP needs m1/m2 (s1 in-order)

    for (int half = 0; half < 2; half++) {
        cudaStream_t sc_ = half ? s1 : s0;
        const long long bo = (long long)half * 2;       // batch offset
        const long long ro = bo * TQ;                   // row offset (BT rows)

        // cross scores
        gemm_t2<0,true,false><<<dim3(SK/128, TQ/128, 2*HH), 256, SM_T2, sc_>>>(
            q2h + ro*DM, q2l + ro*DM, DM, (long long)TQ*DM, HD,
            kv2h + bo*SK*2*DM, kv2l + bo*SK*2*DM, 2*DM, (long long)SK*2*DM, HD,
            scores + bo*TSb, nullptr, nullptr, SK, TSb, TSh,
            nullptr, nullptr, 0, HD, 0.125f, HH);

        // fused softmax + out2
        softmax_fused<<<dim3(TQ/8, 2), 256, 0, sc_>>>(
            scores + bo*TSb, en_mask + bo*SK, tvn + bo*SK,
            ph + bo*TSb, pl + bo*TSb, out2 + ro*SK);

        // PV
        gemm_t2n<64,false,true><<<dim3(1, TQ/128, 2*HH), 256, SM_T2N64, sc_>>>(
            ph + bo*TSb, pl + bo*TSb, SK, TSb, TSh,
            kv2h + DM + bo*SK*2*DM, kv2l + DM + bo*SK*2*DM, 2*DM, (long long)SK*2*DM, HD,
            nullptr, ctxh + ro*DM, ctxl + ro*DM, DM, (long long)TQ*DM, HD,
            nullptr, nullptr, 0, SK, 1.0f, HH);

        // proj2: x2 = x + ctx @ w_out2^T + b_out2   (rows of this half)
        gemm_t2<0,true,false><<<dim3(DM/128, (BT/2)/128, 1), 256, SM_T2, sc_>>>(
            ctxh + ro*DM, ctxl + ro*DM, DM, 0, 0,  wo2h, wo2l, DM, 0, 0,
            x2 + ro*DM, nullptr, nullptr, DM, 0, 0,
            b_out2, x + ro*DM, DM, DM, 1.0f, 1);

        // lnx
        ln_split<<<BT/2, 256, 0, sc_>>>(x2 + ro*DM, lnxh + ro*DM, lnxl + ro*DM, ln_g, ln_b);

        // MLP1: h = gelu(lnx @ mlp_w1^T + b1)
        gemm_t2<1,false,true><<<dim3(4*DM/128, (BT/2)/128, 1), 256, SM_T2, sc_>>>(
            lnxh + ro*DM, lnxl + ro*DM, DM, 0, 0,  m1h, m1l, DM, 0, 0,
            nullptr, hhp + ro*4*DM, hlp + ro*4*DM, 4*DM, 0, 0,
            mlp_b1, nullptr, 0, DM, 1.0f, 1);

        // MLP2: out1 = x2 + h @ mlp_w2^T + b2
        gemm_t2<0,true,false><<<dim3(DM/128, (BT/2)/128, 1), 256, SM_T2, sc_>>>(
            hhp + ro*4*DM, hlp + ro*4*DM, 4*DM, 0, 0,  m2h, m2l, 4*DM, 0, 0,
            out1 + ro*DM, nullptr, nullptr, DM, 0, 0,
            mlp_b2, x2 + ro*DM, DM, 4*DM, 1.0f, 1);
    }

    // join: graph end must include s1's chain
    cudaEventRecord(g_evS1d, s1);
    cudaStreamWaitEvent(s0, g_evS1d, 0);
}